// round 12
// baseline (speedup 1.0000x reference)
#include <cuda_runtime.h>
#include <cuda_fp16.h>
#include <math.h>
#include <stdint.h>

#define BB 256
#define HH 512
#define NNODES 128
#define NCTA 128

// ============================================================================
// PTX helpers (sm_80+ only — tcgen05 is sm_103a-gated, harness emits compute_103)
// ============================================================================
__device__ __forceinline__ uint32_t smem_u32(const void* p) {
    uint32_t a;
    asm("{ .reg .u64 t; cvta.to.shared.u64 t, %1; cvt.u32.u64 %0, t; }" : "=r"(a) : "l"(p));
    return a;
}
__device__ __forceinline__ void cp16(uint32_t saddr, const void* g) {
    asm volatile("cp.async.cg.shared.global [%0], [%1], 16;" :: "r"(saddr), "l"(g));
}
#define CP_COMMIT() asm volatile("cp.async.commit_group;" ::: "memory")
#define LDSM4(r, a) asm volatile("ldmatrix.sync.aligned.m8n8.x4.shared.b16 {%0,%1,%2,%3}, [%4];" \
    : "=r"((r)[0]), "=r"((r)[1]), "=r"((r)[2]), "=r"((r)[3]) : "r"(a))

__device__ __forceinline__ void mma16816(float* c, const uint32_t* a, const uint32_t* b) {
    asm volatile("mma.sync.aligned.m16n8k16.row.col.f32.f16.f16.f32 "
                 "{%0,%1,%2,%3}, {%4,%5,%6,%7}, {%8,%9}, {%0,%1,%2,%3};"
                 : "+f"(c[0]), "+f"(c[1]), "+f"(c[2]), "+f"(c[3])
                 : "r"(a[0]), "r"(a[1]), "r"(a[2]), "r"(a[3]), "r"(b[0]), "r"(b[1]));
}

// ============================================================================
// Device globals
// ============================================================================
__device__ __align__(16) __half g_W0[2048 * 640];       // fp16 weights (packed cols)
__device__ __align__(16) __half g_W1[2048 * 1024];
__device__ __align__(16) float g_W1ft[512 * 512], g_W2ft[512 * 1024];
__device__ __align__(16) float g_bg0[2048], g_bg1[2048];
__device__ __align__(16) __half g_H0[2][BB * HH];       // fp16 activations
__device__ __align__(16) __half g_H1[2][BB * HH];
__device__ __align__(16) __half g_DEC[2][BB * 128];
__device__ __align__(16) float g_c0[BB * HH], g_c1[BB * HH], g_h1f[BB * HH];
__device__ __align__(16) float g_t[BB * 512], g_hx[BB * 1024];
__device__ unsigned char g_used[BB * NNODES];
// all-flag grid barrier: one flag per CTA, monotonic across graph replays
__device__ __align__(128) unsigned g_bar[NCTA];

__device__ __forceinline__ float sigf(float v) { return 1.f / (1.f + expf(-v)); }

// Flag grid barrier: each CTA release-stores its own flag (no atomic
// serialization); threads 0..127 acquire-poll one flag each. Barrier
// completes one L2 round trip after the last arrival.
__device__ __forceinline__ void grid_sync(unsigned target) {
    __syncthreads();
    if (threadIdx.x == 0)
        asm volatile("st.release.gpu.global.u32 [%0], %1;"
                     :: "l"(g_bar + blockIdx.x), "r"(target) : "memory");
    if (threadIdx.x < NCTA) {
        unsigned v;
        asm volatile("ld.acquire.gpu.global.u32 %0, [%1];"
                     : "=r"(v) : "l"(g_bar + threadIdx.x) : "memory");
        while (v < target) {
            __nanosleep(32);
            asm volatile("ld.acquire.gpu.global.u32 %0, [%1];"
                         : "=r"(v) : "l"(g_bar + threadIdx.x) : "memory");
        }
    }
    __syncthreads();
}

// ============================================================================
// Weight prep. Packed column layout: pc = G*32 + gate*8 + u  (G=h/8, u=h%8),
// n_orig = gate*512 + G*8 + u. One warp's 32 cols = all 4 gates of 8 hidden.
// ============================================================================
__global__ void prep_weights(const float* __restrict__ Wih0, const float* __restrict__ Whh0,
                             const float* __restrict__ bih0, const float* __restrict__ bhh0,
                             const float* __restrict__ Wih1, const float* __restrict__ Whh1,
                             const float* __restrict__ bih1, const float* __restrict__ bhh1,
                             const float* __restrict__ W1,   const float* __restrict__ W2)
{
    const long S0 = 2048L * 640;
    const long S1 = S0 + 2048L * 1024;
    const long S2 = S1 + 512L * 512;
    const long S3 = S2 + 512L * 1024;
    const long S4 = S3 + 2048;
    const long S5 = S4 + 2048;
    long stride = (long)gridDim.x * blockDim.x;
    for (long i = (long)blockIdx.x * blockDim.x + threadIdx.x; i < S5; i += stride) {
        if (i < S0) {
            long r = i; int pc = (int)(r / 640), k = (int)(r % 640);
            int n = ((pc >> 3) & 3) * 512 + (pc >> 5) * 8 + (pc & 7);
            float w = (k < 128) ? Wih0[(long)n * 128 + k] : Whh0[(long)n * 512 + (k - 128)];
            g_W0[r] = __float2half_rn(w);
        } else if (i < S1) {
            long r = i - S0; int pc = (int)(r / 1024), k = (int)(r % 1024);
            int n = ((pc >> 3) & 3) * 512 + (pc >> 5) * 8 + (pc & 7);
            float w = (k < 512) ? Wih1[(long)n * 512 + k] : Whh1[(long)n * 512 + (k - 512)];
            g_W1[r] = __float2half_rn(w);
        } else if (i < S2) {
            long r = i - S1; int k = (int)(r / 512), j = (int)(r % 512);
            g_W1ft[r] = W1[(long)j * 512 + k];
        } else if (i < S3) {
            long r = i - S2; int k = (int)(r / 1024), j = (int)(r % 1024);
            g_W2ft[r] = W2[(long)j * 512 + k];
        } else if (i < S4) {
            int pc = (int)(i - S3);
            int n = ((pc >> 3) & 3) * 512 + (pc >> 5) * 8 + (pc & 7);
            g_bg0[pc] = bih0[n] + bhh0[n];
        } else {
            int pc = (int)(i - S4);
            int n = ((pc >> 3) & 3) * 512 + (pc >> 5) * 8 + (pc & 7);
            g_bg1[pc] = bih1[n] + bhh1[n];
        }
    }
}

// ============================================================================
// State init (buffers index 1 = "prev" for step 0)
// ============================================================================
__global__ void init_state()
{
    int i = blockIdx.x * blockDim.x + threadIdx.x;
    if (i >= BB * HH) return;
    int b = i >> 9, h = i & 511;
    g_c0[i] = 0.f;
    g_c1[i] = 0.f;
    g_H0[1][i] = __float2half_rn(g_hx[b * 1024 + h]);
    g_H1[1][i] = __float2half_rn(g_hx[b * 1024 + 512 + h]);
    if (h < 128) {
        g_DEC[1][b * 128 + h] = __float2half_rn(0.f);
        g_used[b * 128 + h] = 0;
    }
}

// ============================================================================
// fp32 SGEMM for the one-time FNN init
// ============================================================================
#define TBM 64
#define TBN 64
#define TBK 16
__global__ __launch_bounds__(256) void sgemm_bias(
    const float* __restrict__ A, const float* __restrict__ Bm,
    const float* __restrict__ bias, float* __restrict__ C,
    int M, int N, int K, int lda, int relu)
{
    __shared__ __align__(16) float As[TBK][TBM + 4];
    __shared__ __align__(16) float Bs[TBK][TBN + 4];
    const int t = threadIdx.x;
    const int bM = blockIdx.y * TBM, bN = blockIdx.x * TBN;
    const int tx = t & 15, ty = t >> 4;
    const int arow = t >> 2, ak = (t & 3) * 4;
    const int bk = t >> 4, bn = (t & 15) * 4;
    float acc[4][4];
#pragma unroll
    for (int i = 0; i < 4; i++)
#pragma unroll
        for (int j = 0; j < 4; j++) acc[i][j] = 0.f;
    for (int k0 = 0; k0 < K; k0 += TBK) {
        float4 a4 = *reinterpret_cast<const float4*>(A + (long)(bM + arow) * lda + k0 + ak);
        As[ak + 0][arow] = a4.x; As[ak + 1][arow] = a4.y;
        As[ak + 2][arow] = a4.z; As[ak + 3][arow] = a4.w;
        *reinterpret_cast<float4*>(&Bs[bk][bn]) =
            *reinterpret_cast<const float4*>(Bm + (long)(k0 + bk) * N + bN + bn);
        __syncthreads();
#pragma unroll
        for (int kk = 0; kk < TBK; kk++) {
            float4 av = *reinterpret_cast<const float4*>(&As[kk][ty * 4]);
            float4 bv = *reinterpret_cast<const float4*>(&Bs[kk][tx * 4]);
            float a[4] = {av.x, av.y, av.z, av.w};
            float b[4] = {bv.x, bv.y, bv.z, bv.w};
#pragma unroll
            for (int i = 0; i < 4; i++)
#pragma unroll
                for (int j = 0; j < 4; j++) acc[i][j] = fmaf(a[i], b[j], acc[i][j]);
        }
        __syncthreads();
    }
    float4 bv = *reinterpret_cast<const float4*>(bias + bN + tx * 4);
    float bb[4] = {bv.x, bv.y, bv.z, bv.w};
#pragma unroll
    for (int i = 0; i < 4; i++) {
        float4 o;
        o.x = acc[i][0] + bb[0]; o.y = acc[i][1] + bb[1];
        o.z = acc[i][2] + bb[2]; o.w = acc[i][3] + bb[3];
        if (relu) { o.x = fmaxf(o.x, 0.f); o.y = fmaxf(o.y, 0.f);
                    o.z = fmaxf(o.z, 0.f); o.w = fmaxf(o.w, 0.f); }
        *reinterpret_cast<float4*>(C + (long)(bM + ty * 4 + i) * N + bN + tx * 4) = o;
    }
}

// ============================================================================
// Persistent decode loop: 128 CTAs x 256 threads (8 warps, warp grid 2x4,
// warp tile 16x32). CTA tile 32(M)x128(N). KC=64 double-buffered cp.async.
// 1-pass fp16 GEMM (4 HMMA per kk), LSTM cell in epilogue.
// Identical to the 6206us kernel except the grid barrier is flag-based.
// stage = A 4K | B 16K = 20K; x2 = 40K dynamic smem.
// ============================================================================
#define STAGE 20480
#define GEMM_SMEM (2 * STAGE + 1024)

__device__ __forceinline__ void load_a_tile(uint32_t sdst,
    const __half* s1, int str1, int ksplit,
    const __half* s2, int str2, int k0, int mt, int t)
{
    int r = t >> 3;
    int cb = (t & 7) << 4;
    int row = mt * 32 + r;
    const char* src = (k0 < ksplit)
        ? (const char*)(s1 + (long)row * str1 + k0) + cb
        : (const char*)(s2 + (long)row * str2 + (k0 - ksplit)) + cb;
    cp16(sdst + r * 128 + (cb ^ ((r & 7) << 4)), src);
}

__device__ __forceinline__ void load_b_tile(uint32_t sdst, const __half* w,
                                            int K, int k0, int nt, int t)
{
#pragma unroll
    for (int i = 0; i < 4; i++) {
        int idx = i * 256 + t;
        int r = idx >> 3;
        int cb = (idx & 7) << 4;
        cp16(sdst + r * 128 + (cb ^ ((r & 7) << 4)),
             (const char*)(w + (long)(nt * 128 + r) * K + k0) + cb);
    }
}

__device__ __forceinline__ void gemm_cell_phase(uint32_t base,
    const __half* A1, int str1, int ksplit,
    const __half* A2, int str2,
    const __half* W, int K,
    const float* __restrict__ bg,
    float* __restrict__ cst, __half* __restrict__ hh,
    float* __restrict__ hf, int mt, int nt)
{
    const int t = threadIdx.x;
    const int lane = t & 31, wid = t >> 5;
    const int wm = wid >> 2, wn = wid & 3;
    const int nch = K >> 6;

    float acc[4][4];
#pragma unroll
    for (int j = 0; j < 4; j++)
#pragma unroll
        for (int v = 0; v < 4; v++) acc[j][v] = 0.f;

    const int rA = wm * 16 + ((lane >> 3) & 1) * 8 + (lane & 7);
    const int cA = (lane >> 4) * 16;
    const int gB = lane >> 3;
    const int rBb = (gB >> 1) * 8 + (lane & 7);
    const int cB = (gB & 1) * 16;

    // prologue: chunk 0
    {
        load_a_tile(base, A1, str1, ksplit, A2, str2, 0, mt, t);
        load_b_tile(base + 4096, W, K, 0, nt, t);
        CP_COMMIT();
    }

    for (int c = 0; c < nch; c++) {
        if (c + 1 < nch) {
            uint32_t nb = base + ((c + 1) & 1) * STAGE;
            int k0 = (c + 1) * 64;
            load_a_tile(nb, A1, str1, ksplit, A2, str2, k0, mt, t);
            load_b_tile(nb + 4096, W, K, k0, nt, t);
            CP_COMMIT();
            asm volatile("cp.async.wait_group 1;" ::: "memory");
        } else {
            asm volatile("cp.async.wait_group 0;" ::: "memory");
        }
        __syncthreads();

        uint32_t bb = base + (c & 1) * STAGE;
#pragma unroll
        for (int kk = 0; kk < 4; kk++) {
            uint32_t ah[4], bh[2][4];
            {
                uint32_t offA = (uint32_t)(rA * 128 + ((kk * 32 + cA) ^ ((rA & 7) << 4)));
                LDSM4(ah, bb + offA);
            }
#pragma unroll
            for (int jj = 0; jj < 2; jj++) {
                int r = wn * 32 + jj * 16 + rBb;
                uint32_t offB = (uint32_t)(r * 128 + ((kk * 32 + cB) ^ ((r & 7) << 4)));
                LDSM4(bh[jj], bb + 4096 + offB);
            }
#pragma unroll
            for (int j = 0; j < 4; j++) {
                const uint32_t* bj = &bh[j >> 1][(j & 1) * 2];
                mma16816(acc[j], ah, bj);
            }
        }
        __syncthreads();
    }

    // Epilogue: LSTM cell from fragments. thread owns (b0,b0+8) x (h, h+1),
    // gates j=0..3 in acc[j].
    const int b0 = mt * 32 + wm * 16 + (lane >> 2);
    const int h0i = (nt * 4 + wn) * 8 + 2 * (lane & 3);
    const int pcb = nt * 128 + wn * 32 + 2 * (lane & 3);
    float bi[4][2];
#pragma unroll
    for (int j = 0; j < 4; j++) {
        bi[j][0] = bg[pcb + j * 8];
        bi[j][1] = bg[pcb + j * 8 + 1];
    }
#pragma unroll
    for (int half = 0; half < 2; half++) {
        int b = b0 + half * 8;
        float hn[2];
#pragma unroll
        for (int u = 0; u < 2; u++) {
            int v = half * 2 + u;
            float iv = acc[0][v] + bi[0][u];
            float fv = acc[1][v] + bi[1][u];
            float gv = acc[2][v] + bi[2][u];
            float ov = acc[3][v] + bi[3][u];
            long ci = (long)b * 512 + h0i + u;
            float cn = sigf(fv) * cst[ci] + sigf(iv) * tanhf(gv);
            cst[ci] = cn;
            hn[u] = sigf(ov) * tanhf(cn);
        }
        long hi = (long)b * 512 + h0i;
        *reinterpret_cast<__half2*>(hh + hi) =
            __half2(__float2half_rn(hn[0]), __float2half_rn(hn[1]));
        if (hf) *reinterpret_cast<float2*>(hf + hi) = make_float2(hn[0], hn[1]);
    }
}

__global__ __launch_bounds__(256, 1) void decode_loop(
    const float* __restrict__ node, const float* __restrict__ Wo,
    const float* __restrict__ bo, float* __restrict__ out)
{
    extern __shared__ char dsm[];
    uint32_t base = (smem_u32(dsm) + 1023) & ~1023u;
    __shared__ float s_h1[1024];
    __shared__ float s_x[256], s_d[256];
    __shared__ int   s_i[256];

    const int t = threadIdx.x;
    const int bid = blockIdx.x;
    const int mt = bid >> 4, nt = bid & 15;
    const int q = t >> 7, n = t & 127;   // tail: 2 batches per CTA

    unsigned bt;
    asm("ld.global.u32 %0, [%1];" : "=r"(bt) : "l"(g_bar + bid));

    for (int s = 0; s < NNODES; s++) {
        const int cur = s & 1, prev = cur ^ 1;

        // Phase A: gates0 = [dec|h0] @ W0p -> cell0 -> H0[cur]
        gemm_cell_phase(base,
            g_DEC[prev], 128, 128,
            g_H0[prev],  512,
            g_W0, 640, g_bg0,
            g_c0, g_H0[cur], nullptr, mt, nt);
        grid_sync(++bt);

        // Phase B: gates1 = [h0_new|h1_prev] @ W1p -> cell1 -> H1[cur] + h1f
        gemm_cell_phase(base,
            g_H0[cur], 512, 512,
            g_H1[prev], 512,
            g_W1, 1024, g_bg1,
            g_c1, g_H1[cur], g_h1f, mt, nt);
        grid_sync(++bt);

        // Tail: projection + masked argmin + scatter + dec feedback
        {
            const int b = bid * 2 + q;
#pragma unroll
            for (int j = 0; j < 4; j++)
                s_h1[q * 512 + n + j * 128] = g_h1f[(long)b * 512 + n + j * 128];
            __syncthreads();
            float accp = bo[n];
            const float4* wr = reinterpret_cast<const float4*>(Wo + (long)n * 512);
            const float4* hv = reinterpret_cast<const float4*>(s_h1 + q * 512);
#pragma unroll 4
            for (int kq = 0; kq < 128; kq++) {
                float4 w = wr[kq], h4 = hv[kq];
                accp = fmaf(w.x, h4.x, accp); accp = fmaf(w.y, h4.y, accp);
                accp = fmaf(w.z, h4.z, accp); accp = fmaf(w.w, h4.w, accp);
            }
            s_x[q * 128 + n] = accp;
            __syncthreads();
            float dist = 3.4e38f;
            if (!g_used[b * 128 + n]) {
                const float* nd = node + ((long)b * 128 + n) * 128;
                const float* xsb = s_x + q * 128;
                float sum = 0.f;
#pragma unroll 8
                for (int d = 0; d < 128; d++) {
                    float df = xsb[d] - nd[d];
                    sum = fmaf(df, df, sum);
                }
                dist = sum;
            }
            s_d[q * 128 + n] = dist;
            s_i[q * 128 + n] = n;
            __syncthreads();
#pragma unroll
            for (int st_ = 64; st_ > 0; st_ >>= 1) {
                if (n < st_) {
                    float ov = s_d[q * 128 + n + st_]; int oi = s_i[q * 128 + n + st_];
                    if (ov < s_d[q * 128 + n] ||
                        (ov == s_d[q * 128 + n] && oi < s_i[q * 128 + n])) {
                        s_d[q * 128 + n] = ov; s_i[q * 128 + n] = oi;
                    }
                }
                __syncthreads();
            }
            int idx = s_i[q * 128];
            if (n == 0) g_used[b * 128 + idx] = 1;
            float xv = s_x[q * 128 + n];
            out[((long)b * 128 + idx) * 128 + n] = xv;
            g_DEC[cur][b * 128 + n] = __float2half_rn(xv);
        }
        grid_sync(++bt);
    }
}

// ============================================================================
// Launch
// ============================================================================
extern "C" void kernel_launch(void* const* d_in, const int* in_sizes, int n_in,
                              void* d_out, int out_size)
{
    const float* emb  = (const float*)d_in[0];
    const float* node = (const float*)d_in[1];
    const float* W1   = (const float*)d_in[2];
    const float* b1   = (const float*)d_in[3];
    const float* W2   = (const float*)d_in[4];
    const float* b2   = (const float*)d_in[5];
    const float* Wih0 = (const float*)d_in[6];
    const float* Whh0 = (const float*)d_in[7];
    const float* bih0 = (const float*)d_in[8];
    const float* bhh0 = (const float*)d_in[9];
    const float* Wih1 = (const float*)d_in[10];
    const float* Whh1 = (const float*)d_in[11];
    const float* bih1 = (const float*)d_in[12];
    const float* bhh1 = (const float*)d_in[13];
    const float* Wo   = (const float*)d_in[14];
    const float* bo   = (const float*)d_in[15];
    float* out = (float*)d_out;

    cudaFuncSetAttribute(decode_loop, cudaFuncAttributeMaxDynamicSharedMemorySize, GEMM_SMEM);

    float *pW1ft, *pW2ft, *pt, *phx;
    cudaGetSymbolAddress((void**)&pW1ft, g_W1ft);
    cudaGetSymbolAddress((void**)&pW2ft, g_W2ft);
    cudaGetSymbolAddress((void**)&pt,    g_t);
    cudaGetSymbolAddress((void**)&phx,   g_hx);

    prep_weights<<<2048, 256>>>(Wih0, Whh0, bih0, bhh0, Wih1, Whh1, bih1, bhh1, W1, W2);
    sgemm_bias<<<dim3(512 / TBN, BB / TBM), 256>>>(emb, pW1ft, b1, pt, BB, 512, 512, 512, 1);
    sgemm_bias<<<dim3(1024 / TBN, BB / TBM), 256>>>(pt, pW2ft, b2, phx, BB, 1024, 512, 512, 0);
    init_state<<<(BB * HH) / 256, 256>>>();

    decode_loop<<<NCTA, 256, GEMM_SMEM>>>(node, Wo, bo, out);
}

// round 13
// speedup vs baseline: 1.2307x; 1.2307x over previous
#include <cuda_runtime.h>
#include <cuda_fp16.h>
#include <math.h>
#include <stdint.h>

#define BB 256
#define HH 512
#define NNODES 128
#define NCTA 128

// ============================================================================
// PTX helpers (sm_80+ only — tcgen05 is sm_103a-gated, harness emits compute_103)
// ============================================================================
__device__ __forceinline__ uint32_t smem_u32(const void* p) {
    uint32_t a;
    asm("{ .reg .u64 t; cvta.to.shared.u64 t, %1; cvt.u32.u64 %0, t; }" : "=r"(a) : "l"(p));
    return a;
}
__device__ __forceinline__ void cp16(uint32_t saddr, const void* g) {
    asm volatile("cp.async.cg.shared.global [%0], [%1], 16;" :: "r"(saddr), "l"(g));
}
#define CP_COMMIT() asm volatile("cp.async.commit_group;" ::: "memory")
#define LDSM4(r, a) asm volatile("ldmatrix.sync.aligned.m8n8.x4.shared.b16 {%0,%1,%2,%3}, [%4];" \
    : "=r"((r)[0]), "=r"((r)[1]), "=r"((r)[2]), "=r"((r)[3]) : "r"(a))

__device__ __forceinline__ void mma16816(float* c, const uint32_t* a, const uint32_t* b) {
    asm volatile("mma.sync.aligned.m16n8k16.row.col.f32.f16.f16.f32 "
                 "{%0,%1,%2,%3}, {%4,%5,%6,%7}, {%8,%9}, {%0,%1,%2,%3};"
                 : "+f"(c[0]), "+f"(c[1]), "+f"(c[2]), "+f"(c[3])
                 : "r"(a[0]), "r"(a[1]), "r"(a[2]), "r"(a[3]), "r"(b[0]), "r"(b[1]));
}

// ============================================================================
// Device globals
// ============================================================================
__device__ __align__(16) __half g_W0[2048 * 640];       // fp16 weights (packed cols)
__device__ __align__(16) __half g_W1[2048 * 1024];
__device__ __align__(16) float g_W1ft[512 * 512], g_W2ft[512 * 1024];
__device__ __align__(16) float g_bg0[2048], g_bg1[2048];
__device__ __align__(16) __half g_H0[2][BB * HH];       // fp16 activations
__device__ __align__(16) __half g_H1[2][BB * HH];
__device__ __align__(16) __half g_DEC[2][BB * 128];
__device__ __align__(16) float g_c0[BB * HH], g_c1[BB * HH], g_h1f[BB * HH];
__device__ unsigned char g_used[BB * NNODES];

// grid barrier state (zero-initialized at module load; self-consistent across replays)
__device__ unsigned g_cnt;
__device__ volatile unsigned g_gen;

__device__ __forceinline__ void grid_sync() {
    __syncthreads();
    if (threadIdx.x == 0) {
        __threadfence();
        unsigned gen = g_gen;
        if (atomicAdd(&g_cnt, 1u) == NCTA - 1) {
            atomicExch(&g_cnt, 0u);
            __threadfence();
            g_gen = gen + 1;
        } else {
            while (g_gen == gen) { __nanosleep(32); }
        }
        __threadfence();
    }
    __syncthreads();
}

__device__ __forceinline__ float sigf(float v) { return 1.f / (1.f + expf(-v)); }

// ============================================================================
// Weight prep. Packed column layout: pc = G*32 + gate*8 + u  (G=h/8, u=h%8),
// n_orig = gate*512 + G*8 + u. One warp's 32 cols = all 4 gates of 8 hidden.
// ============================================================================
__global__ void prep_weights(const float* __restrict__ Wih0, const float* __restrict__ Whh0,
                             const float* __restrict__ bih0, const float* __restrict__ bhh0,
                             const float* __restrict__ Wih1, const float* __restrict__ Whh1,
                             const float* __restrict__ bih1, const float* __restrict__ bhh1,
                             const float* __restrict__ W1,   const float* __restrict__ W2)
{
    const long S0 = 2048L * 640;
    const long S1 = S0 + 2048L * 1024;
    const long S2 = S1 + 512L * 512;
    const long S3 = S2 + 512L * 1024;
    const long S4 = S3 + 2048;
    const long S5 = S4 + 2048;
    long stride = (long)gridDim.x * blockDim.x;
    for (long i = (long)blockIdx.x * blockDim.x + threadIdx.x; i < S5; i += stride) {
        if (i < S0) {
            long r = i; int pc = (int)(r / 640), k = (int)(r % 640);
            int n = ((pc >> 3) & 3) * 512 + (pc >> 5) * 8 + (pc & 7);
            float w = (k < 128) ? Wih0[(long)n * 128 + k] : Whh0[(long)n * 512 + (k - 128)];
            g_W0[r] = __float2half_rn(w);
        } else if (i < S1) {
            long r = i - S0; int pc = (int)(r / 1024), k = (int)(r % 1024);
            int n = ((pc >> 3) & 3) * 512 + (pc >> 5) * 8 + (pc & 7);
            float w = (k < 512) ? Wih1[(long)n * 512 + k] : Whh1[(long)n * 512 + (k - 512)];
            g_W1[r] = __float2half_rn(w);
        } else if (i < S2) {
            long r = i - S1; int k = (int)(r / 512), j = (int)(r % 512);
            g_W1ft[r] = W1[(long)j * 512 + k];
        } else if (i < S3) {
            long r = i - S2; int k = (int)(r / 1024), j = (int)(r % 1024);
            g_W2ft[r] = W2[(long)j * 512 + k];
        } else if (i < S4) {
            int pc = (int)(i - S3);
            int n = ((pc >> 3) & 3) * 512 + (pc >> 5) * 8 + (pc & 7);
            g_bg0[pc] = bih0[n] + bhh0[n];
        } else {
            int pc = (int)(i - S4);
            int n = ((pc >> 3) & 3) * 512 + (pc >> 5) * 8 + (pc & 7);
            g_bg1[pc] = bih1[n] + bhh1[n];
        }
    }
}

// ============================================================================
// Persistent decode loop: 128 CTAs x 256 threads (8 warps, warp grid 2x4,
// warp tile 16x32). CTA tile 32(M)x128(N). KC=64 double-buffered cp.async.
// 1-pass fp16 GEMM (4 HMMA per kk), LSTM cell in epilogue.
// Hot loop byte-identical to the 6206us kernel. NEW: FNN init + state init
// folded into the kernel prologue, so each kernel_launch emits only
// [prep_weights, decode_loop] — making ncu (-s 5 -c 1) capture decode_loop.
// stage = A 4K | B 16K = 20K; x2 = 40K dynamic smem.
// ============================================================================
#define STAGE 20480
#define GEMM_SMEM (2 * STAGE + 1024)

__device__ __forceinline__ void load_a_tile(uint32_t sdst,
    const __half* s1, int str1, int ksplit,
    const __half* s2, int str2, int k0, int mt, int t)
{
    int r = t >> 3;
    int cb = (t & 7) << 4;
    int row = mt * 32 + r;
    const char* src = (k0 < ksplit)
        ? (const char*)(s1 + (long)row * str1 + k0) + cb
        : (const char*)(s2 + (long)row * str2 + (k0 - ksplit)) + cb;
    cp16(sdst + r * 128 + (cb ^ ((r & 7) << 4)), src);
}

__device__ __forceinline__ void load_b_tile(uint32_t sdst, const __half* w,
                                            int K, int k0, int nt, int t)
{
#pragma unroll
    for (int i = 0; i < 4; i++) {
        int idx = i * 256 + t;
        int r = idx >> 3;
        int cb = (idx & 7) << 4;
        cp16(sdst + r * 128 + (cb ^ ((r & 7) << 4)),
             (const char*)(w + (long)(nt * 128 + r) * K + k0) + cb);
    }
}

__device__ __forceinline__ void gemm_cell_phase(uint32_t base,
    const __half* A1, int str1, int ksplit,
    const __half* A2, int str2,
    const __half* W, int K,
    const float* __restrict__ bg,
    float* __restrict__ cst, __half* __restrict__ hh,
    float* __restrict__ hf, int mt, int nt)
{
    const int t = threadIdx.x;
    const int lane = t & 31, wid = t >> 5;
    const int wm = wid >> 2, wn = wid & 3;
    const int nch = K >> 6;

    float acc[4][4];
#pragma unroll
    for (int j = 0; j < 4; j++)
#pragma unroll
        for (int v = 0; v < 4; v++) acc[j][v] = 0.f;

    const int rA = wm * 16 + ((lane >> 3) & 1) * 8 + (lane & 7);
    const int cA = (lane >> 4) * 16;
    const int gB = lane >> 3;
    const int rBb = (gB >> 1) * 8 + (lane & 7);
    const int cB = (gB & 1) * 16;

    // prologue: chunk 0
    {
        load_a_tile(base, A1, str1, ksplit, A2, str2, 0, mt, t);
        load_b_tile(base + 4096, W, K, 0, nt, t);
        CP_COMMIT();
    }

    for (int c = 0; c < nch; c++) {
        if (c + 1 < nch) {
            uint32_t nb = base + ((c + 1) & 1) * STAGE;
            int k0 = (c + 1) * 64;
            load_a_tile(nb, A1, str1, ksplit, A2, str2, k0, mt, t);
            load_b_tile(nb + 4096, W, K, k0, nt, t);
            CP_COMMIT();
            asm volatile("cp.async.wait_group 1;" ::: "memory");
        } else {
            asm volatile("cp.async.wait_group 0;" ::: "memory");
        }
        __syncthreads();

        uint32_t bb = base + (c & 1) * STAGE;
#pragma unroll
        for (int kk = 0; kk < 4; kk++) {
            uint32_t ah[4], bh[2][4];
            {
                uint32_t offA = (uint32_t)(rA * 128 + ((kk * 32 + cA) ^ ((rA & 7) << 4)));
                LDSM4(ah, bb + offA);
            }
#pragma unroll
            for (int jj = 0; jj < 2; jj++) {
                int r = wn * 32 + jj * 16 + rBb;
                uint32_t offB = (uint32_t)(r * 128 + ((kk * 32 + cB) ^ ((r & 7) << 4)));
                LDSM4(bh[jj], bb + 4096 + offB);
            }
#pragma unroll
            for (int j = 0; j < 4; j++) {
                const uint32_t* bj = &bh[j >> 1][(j & 1) * 2];
                mma16816(acc[j], ah, bj);
            }
        }
        __syncthreads();
    }

    // Epilogue: LSTM cell from fragments. thread owns (b0,b0+8) x (h, h+1),
    // gates j=0..3 in acc[j].
    const int b0 = mt * 32 + wm * 16 + (lane >> 2);
    const int h0i = (nt * 4 + wn) * 8 + 2 * (lane & 3);
    const int pcb = nt * 128 + wn * 32 + 2 * (lane & 3);
    float bi[4][2];
#pragma unroll
    for (int j = 0; j < 4; j++) {
        bi[j][0] = bg[pcb + j * 8];
        bi[j][1] = bg[pcb + j * 8 + 1];
    }
#pragma unroll
    for (int half = 0; half < 2; half++) {
        int b = b0 + half * 8;
        float hn[2];
#pragma unroll
        for (int u = 0; u < 2; u++) {
            int v = half * 2 + u;
            float iv = acc[0][v] + bi[0][u];
            float fv = acc[1][v] + bi[1][u];
            float gv = acc[2][v] + bi[2][u];
            float ov = acc[3][v] + bi[3][u];
            long ci = (long)b * 512 + h0i + u;
            float cn = sigf(fv) * cst[ci] + sigf(iv) * tanhf(gv);
            cst[ci] = cn;
            hn[u] = sigf(ov) * tanhf(cn);
        }
        long hi = (long)b * 512 + h0i;
        *reinterpret_cast<__half2*>(hh + hi) =
            __half2(__float2half_rn(hn[0]), __float2half_rn(hn[1]));
        if (hf) *reinterpret_cast<float2*>(hf + hi) = make_float2(hn[0], hn[1]);
    }
}

__global__ __launch_bounds__(256, 1) void decode_loop(
    const float* __restrict__ emb, const float* __restrict__ node,
    const float* __restrict__ Wo, const float* __restrict__ bo,
    const float* __restrict__ b1, const float* __restrict__ b2,
    float* __restrict__ out)
{
    extern __shared__ char dsm[];
    uint32_t base = (smem_u32(dsm) + 1023) & ~1023u;
    __shared__ float s_h1[1024];
    __shared__ float s_x[256], s_d[256];
    __shared__ int   s_i[256];

    const int t = threadIdx.x;
    const int bid = blockIdx.x;
    const int mt = bid >> 4, nt = bid & 15;
    const int q = t >> 7, n = t & 127;   // 2 batches per CTA for init + tail

    // ------------------------------------------------------------------
    // In-kernel FNN init + state init (replaces 3 separate launches).
    // CTA handles batches bid*2 + q.
    // ------------------------------------------------------------------
    {
        float* s_emb = reinterpret_cast<float*>(dsm);         // 1024 floats
        float* s_t   = reinterpret_cast<float*>(dsm) + 1024;  // 1024 floats
        const int b = bid * 2 + q;
#pragma unroll
        for (int m = 0; m < 4; m++)
            s_emb[q * 512 + n + m * 128] = emb[(long)b * 512 + n + m * 128];
        __syncthreads();
        // t = relu(emb @ W1ft + b1)
#pragma unroll
        for (int m = 0; m < 4; m++) {
            int j = n + m * 128;
            float a = b1[j];
            const float* es = s_emb + q * 512;
#pragma unroll 4
            for (int k = 0; k < 512; k++)
                a = fmaf(es[k], g_W1ft[k * 512 + j], a);
            s_t[q * 512 + j] = fmaxf(a, 0.f);
        }
        __syncthreads();
        // hx = t @ W2ft + b2  -> H0[1] (j<512), H1[1] (j>=512)
#pragma unroll
        for (int m = 0; m < 8; m++) {
            int j = n + m * 128;
            float a = b2[j];
            const float* ts = s_t + q * 512;
#pragma unroll 4
            for (int k = 0; k < 512; k++)
                a = fmaf(ts[k], g_W2ft[k * 1024 + j], a);
            if (j < 512) g_H0[1][b * 512 + j] = __float2half_rn(a);
            else         g_H1[1][b * 512 + j - 512] = __float2half_rn(a);
        }
#pragma unroll
        for (int m = 0; m < 4; m++) {
            int h = n + m * 128;
            g_c0[b * 512 + h] = 0.f;
            g_c1[b * 512 + h] = 0.f;
        }
        g_DEC[1][b * 128 + n] = __float2half_rn(0.f);
        g_used[b * 128 + n] = 0;
    }
    grid_sync();

    // ------------------------------------------------------------------
    // Main decode loop (byte-identical to the 6206us kernel)
    // ------------------------------------------------------------------
    for (int s = 0; s < NNODES; s++) {
        const int cur = s & 1, prev = cur ^ 1;

        // Phase A: gates0 = [dec|h0] @ W0p -> cell0 -> H0[cur]
        gemm_cell_phase(base,
            g_DEC[prev], 128, 128,
            g_H0[prev],  512,
            g_W0, 640, g_bg0,
            g_c0, g_H0[cur], nullptr, mt, nt);
        grid_sync();

        // Phase B: gates1 = [h0_new|h1_prev] @ W1p -> cell1 -> H1[cur] + h1f
        gemm_cell_phase(base,
            g_H0[cur], 512, 512,
            g_H1[prev], 512,
            g_W1, 1024, g_bg1,
            g_c1, g_H1[cur], g_h1f, mt, nt);
        grid_sync();

        // Tail: projection + masked argmin + scatter + dec feedback
        {
            const int b = bid * 2 + q;
#pragma unroll
            for (int j = 0; j < 4; j++)
                s_h1[q * 512 + n + j * 128] = g_h1f[(long)b * 512 + n + j * 128];
            __syncthreads();
            float accp = bo[n];
            const float4* wr = reinterpret_cast<const float4*>(Wo + (long)n * 512);
            const float4* hv = reinterpret_cast<const float4*>(s_h1 + q * 512);
#pragma unroll 4
            for (int kq = 0; kq < 128; kq++) {
                float4 w = wr[kq], h4 = hv[kq];
                accp = fmaf(w.x, h4.x, accp); accp = fmaf(w.y, h4.y, accp);
                accp = fmaf(w.z, h4.z, accp); accp = fmaf(w.w, h4.w, accp);
            }
            s_x[q * 128 + n] = accp;
            __syncthreads();
            float dist = 3.4e38f;
            if (!g_used[b * 128 + n]) {
                const float* nd = node + ((long)b * 128 + n) * 128;
                const float* xsb = s_x + q * 128;
                float sum = 0.f;
#pragma unroll 8
                for (int d = 0; d < 128; d++) {
                    float df = xsb[d] - nd[d];
                    sum = fmaf(df, df, sum);
                }
                dist = sum;
            }
            s_d[q * 128 + n] = dist;
            s_i[q * 128 + n] = n;
            __syncthreads();
#pragma unroll
            for (int st_ = 64; st_ > 0; st_ >>= 1) {
                if (n < st_) {
                    float ov = s_d[q * 128 + n + st_]; int oi = s_i[q * 128 + n + st_];
                    if (ov < s_d[q * 128 + n] ||
                        (ov == s_d[q * 128 + n] && oi < s_i[q * 128 + n])) {
                        s_d[q * 128 + n] = ov; s_i[q * 128 + n] = oi;
                    }
                }
                __syncthreads();
            }
            int idx = s_i[q * 128];
            if (n == 0) g_used[b * 128 + idx] = 1;
            float xv = s_x[q * 128 + n];
            out[((long)b * 128 + idx) * 128 + n] = xv;
            g_DEC[cur][b * 128 + n] = __float2half_rn(xv);
        }
        grid_sync();
    }
}

// ============================================================================
// Launch — exactly TWO launches per call so ncu (-s 5 -c 1) lands on
// decode_loop (stream: prep, decode, prep, decode, prep, [decode] <- captured)
// ============================================================================
extern "C" void kernel_launch(void* const* d_in, const int* in_sizes, int n_in,
                              void* d_out, int out_size)
{
    const float* emb  = (const float*)d_in[0];
    const float* node = (const float*)d_in[1];
    const float* W1   = (const float*)d_in[2];
    const float* b1   = (const float*)d_in[3];
    const float* W2   = (const float*)d_in[4];
    const float* b2   = (const float*)d_in[5];
    const float* Wih0 = (const float*)d_in[6];
    const float* Whh0 = (const float*)d_in[7];
    const float* bih0 = (const float*)d_in[8];
    const float* bhh0 = (const float*)d_in[9];
    const float* Wih1 = (const float*)d_in[10];
    const float* Whh1 = (const float*)d_in[11];
    const float* bih1 = (const float*)d_in[12];
    const float* bhh1 = (const float*)d_in[13];
    const float* Wo   = (const float*)d_in[14];
    const float* bo   = (const float*)d_in[15];
    float* out = (float*)d_out;

    cudaFuncSetAttribute(decode_loop, cudaFuncAttributeMaxDynamicSharedMemorySize, GEMM_SMEM);

    prep_weights<<<2048, 256>>>(Wih0, Whh0, bih0, bhh0, Wih1, Whh1, bih1, bhh1, W1, W2);
    decode_loop<<<NCTA, 256, GEMM_SMEM>>>(emb, node, Wo, bo, b1, b2, out);
}

// round 14
// speedup vs baseline: 1.2870x; 1.0457x over previous
#include <cuda_runtime.h>
#include <cuda_fp16.h>
#include <math.h>
#include <stdint.h>

#define BB 256
#define HH 512
#define NNODES 128
#define NCTA 128

// ============================================================================
// PTX helpers (sm_80+ only — tcgen05 is sm_103a-gated, harness emits compute_103)
// ============================================================================
__device__ __forceinline__ uint32_t smem_u32(const void* p) {
    uint32_t a;
    asm("{ .reg .u64 t; cvta.to.shared.u64 t, %1; cvt.u32.u64 %0, t; }" : "=r"(a) : "l"(p));
    return a;
}
__device__ __forceinline__ void cp16(uint32_t saddr, const void* g) {
    asm volatile("cp.async.cg.shared.global [%0], [%1], 16;" :: "r"(saddr), "l"(g));
}
#define CP_COMMIT() asm volatile("cp.async.commit_group;" ::: "memory")
#define LDSM4(r, a) asm volatile("ldmatrix.sync.aligned.m8n8.x4.shared.b16 {%0,%1,%2,%3}, [%4];" \
    : "=r"((r)[0]), "=r"((r)[1]), "=r"((r)[2]), "=r"((r)[3]) : "r"(a))

__device__ __forceinline__ void mma16816(float* c, const uint32_t* a, const uint32_t* b) {
    asm volatile("mma.sync.aligned.m16n8k16.row.col.f32.f16.f16.f32 "
                 "{%0,%1,%2,%3}, {%4,%5,%6,%7}, {%8,%9}, {%0,%1,%2,%3};"
                 : "+f"(c[0]), "+f"(c[1]), "+f"(c[2]), "+f"(c[3])
                 : "r"(a[0]), "r"(a[1]), "r"(a[2]), "r"(a[3]), "r"(b[0]), "r"(b[1]));
}

// ============================================================================
// Device globals
// ============================================================================
__device__ __align__(16) __half g_W0[2048 * 640];       // fp16 weights (packed cols)
__device__ __align__(16) __half g_W1[2048 * 1024];
__device__ __align__(16) float g_W1ft[512 * 512], g_W2ft[512 * 1024];
__device__ __align__(16) float g_bg0[2048], g_bg1[2048];
__device__ __align__(16) __half g_H0[2][BB * HH];       // fp16 activations
__device__ __align__(16) __half g_H1[2][BB * HH];
__device__ __align__(16) __half g_DEC[2][BB * 128];
__device__ __align__(16) float g_c0[BB * HH], g_c1[BB * HH], g_h1f[BB * HH];
__device__ __align__(16) float g_t[BB * 512], g_hx[BB * 1024];
__device__ unsigned char g_used[BB * NNODES];

// grid barrier state (zero-initialized at module load; self-consistent across replays)
__device__ unsigned g_cnt;
__device__ volatile unsigned g_gen;

__device__ __forceinline__ void grid_sync() {
    __syncthreads();
    if (threadIdx.x == 0) {
        __threadfence();
        unsigned gen = g_gen;
        if (atomicAdd(&g_cnt, 1u) == NCTA - 1) {
            atomicExch(&g_cnt, 0u);
            __threadfence();
            g_gen = gen + 1;
        } else {
            while (g_gen == gen) { __nanosleep(32); }
        }
        __threadfence();
    }
    __syncthreads();
}

__device__ __forceinline__ float sigf(float v) { return 1.f / (1.f + expf(-v)); }

// ============================================================================
// Weight prep. Packed column layout: pc = G*32 + gate*8 + u  (G=h/8, u=h%8),
// n_orig = gate*512 + G*8 + u. One warp's 32 cols = all 4 gates of 8 hidden.
// ============================================================================
__global__ void prep_weights(const float* __restrict__ Wih0, const float* __restrict__ Whh0,
                             const float* __restrict__ bih0, const float* __restrict__ bhh0,
                             const float* __restrict__ Wih1, const float* __restrict__ Whh1,
                             const float* __restrict__ bih1, const float* __restrict__ bhh1,
                             const float* __restrict__ W1,   const float* __restrict__ W2)
{
    const long S0 = 2048L * 640;
    const long S1 = S0 + 2048L * 1024;
    const long S2 = S1 + 512L * 512;
    const long S3 = S2 + 512L * 1024;
    const long S4 = S3 + 2048;
    const long S5 = S4 + 2048;
    long stride = (long)gridDim.x * blockDim.x;
    for (long i = (long)blockIdx.x * blockDim.x + threadIdx.x; i < S5; i += stride) {
        if (i < S0) {
            long r = i; int pc = (int)(r / 640), k = (int)(r % 640);
            int n = ((pc >> 3) & 3) * 512 + (pc >> 5) * 8 + (pc & 7);
            float w = (k < 128) ? Wih0[(long)n * 128 + k] : Whh0[(long)n * 512 + (k - 128)];
            g_W0[r] = __float2half_rn(w);
        } else if (i < S1) {
            long r = i - S0; int pc = (int)(r / 1024), k = (int)(r % 1024);
            int n = ((pc >> 3) & 3) * 512 + (pc >> 5) * 8 + (pc & 7);
            float w = (k < 512) ? Wih1[(long)n * 512 + k] : Whh1[(long)n * 512 + (k - 512)];
            g_W1[r] = __float2half_rn(w);
        } else if (i < S2) {
            long r = i - S1; int k = (int)(r / 512), j = (int)(r % 512);
            g_W1ft[r] = W1[(long)j * 512 + k];
        } else if (i < S3) {
            long r = i - S2; int k = (int)(r / 1024), j = (int)(r % 1024);
            g_W2ft[r] = W2[(long)j * 512 + k];
        } else if (i < S4) {
            int pc = (int)(i - S3);
            int n = ((pc >> 3) & 3) * 512 + (pc >> 5) * 8 + (pc & 7);
            g_bg0[pc] = bih0[n] + bhh0[n];
        } else {
            int pc = (int)(i - S4);
            int n = ((pc >> 3) & 3) * 512 + (pc >> 5) * 8 + (pc & 7);
            g_bg1[pc] = bih1[n] + bhh1[n];
        }
    }
}

// ============================================================================
// State init (buffers index 1 = "prev" for step 0)
// ============================================================================
__global__ void init_state()
{
    int i = blockIdx.x * blockDim.x + threadIdx.x;
    if (i >= BB * HH) return;
    int b = i >> 9, h = i & 511;
    g_c0[i] = 0.f;
    g_c1[i] = 0.f;
    g_H0[1][i] = __float2half_rn(g_hx[b * 1024 + h]);
    g_H1[1][i] = __float2half_rn(g_hx[b * 1024 + 512 + h]);
    if (h < 128) {
        g_DEC[1][b * 128 + h] = __float2half_rn(0.f);
        g_used[b * 128 + h] = 0;
    }
}

// ============================================================================
// fp32 SGEMM for the one-time FNN init
// ============================================================================
#define TBM 64
#define TBN 64
#define TBK 16
__global__ __launch_bounds__(256) void sgemm_bias(
    const float* __restrict__ A, const float* __restrict__ Bm,
    const float* __restrict__ bias, float* __restrict__ C,
    int M, int N, int K, int lda, int relu)
{
    __shared__ __align__(16) float As[TBK][TBM + 4];
    __shared__ __align__(16) float Bs[TBK][TBN + 4];
    const int t = threadIdx.x;
    const int bM = blockIdx.y * TBM, bN = blockIdx.x * TBN;
    const int tx = t & 15, ty = t >> 4;
    const int arow = t >> 2, ak = (t & 3) * 4;
    const int bk = t >> 4, bn = (t & 15) * 4;
    float acc[4][4];
#pragma unroll
    for (int i = 0; i < 4; i++)
#pragma unroll
        for (int j = 0; j < 4; j++) acc[i][j] = 0.f;
    for (int k0 = 0; k0 < K; k0 += TBK) {
        float4 a4 = *reinterpret_cast<const float4*>(A + (long)(bM + arow) * lda + k0 + ak);
        As[ak + 0][arow] = a4.x; As[ak + 1][arow] = a4.y;
        As[ak + 2][arow] = a4.z; As[ak + 3][arow] = a4.w;
        *reinterpret_cast<float4*>(&Bs[bk][bn]) =
            *reinterpret_cast<const float4*>(Bm + (long)(k0 + bk) * N + bN + bn);
        __syncthreads();
#pragma unroll
        for (int kk = 0; kk < TBK; kk++) {
            float4 av = *reinterpret_cast<const float4*>(&As[kk][ty * 4]);
            float4 bv = *reinterpret_cast<const float4*>(&Bs[kk][tx * 4]);
            float a[4] = {av.x, av.y, av.z, av.w};
            float b[4] = {bv.x, bv.y, bv.z, bv.w};
#pragma unroll
            for (int i = 0; i < 4; i++)
#pragma unroll
                for (int j = 0; j < 4; j++) acc[i][j] = fmaf(a[i], b[j], acc[i][j]);
        }
        __syncthreads();
    }
    float4 bv = *reinterpret_cast<const float4*>(bias + bN + tx * 4);
    float bb[4] = {bv.x, bv.y, bv.z, bv.w};
#pragma unroll
    for (int i = 0; i < 4; i++) {
        float4 o;
        o.x = acc[i][0] + bb[0]; o.y = acc[i][1] + bb[1];
        o.z = acc[i][2] + bb[2]; o.w = acc[i][3] + bb[3];
        if (relu) { o.x = fmaxf(o.x, 0.f); o.y = fmaxf(o.y, 0.f);
                    o.z = fmaxf(o.z, 0.f); o.w = fmaxf(o.w, 0.f); }
        *reinterpret_cast<float4*>(C + (long)(bM + ty * 4 + i) * N + bN + tx * 4) = o;
    }
}

// ============================================================================
// Persistent decode loop: 128 CTAs x 512 threads. SPLIT-K across two warp
// groups: warps 0-7 (group 0) process chunks [0, nch/2), warps 8-15 (group 1)
// process [nch/2, nch) with the IDENTICAL 16x32 warp tile and inner loop as
// the 6206us kernel. Final cross-group reduction in smem, LSTM epilogue by
// group 0. 4-stage ring (2 per group). Atomic grid barrier (validated best).
// stage = A 4K | B 16K = 20K; x4 = 80K dynamic smem.
// ============================================================================
#define STAGE 20480
#define GEMM_SMEM (4 * STAGE + 1024)

__device__ __forceinline__ void load_a_tile(uint32_t sdst,
    const __half* s1, int str1, int ksplit,
    const __half* s2, int str2, int k0, int mt, int t)
{
    int r = t >> 3;
    int cb = (t & 7) << 4;
    int row = mt * 32 + r;
    const char* src = (k0 < ksplit)
        ? (const char*)(s1 + (long)row * str1 + k0) + cb
        : (const char*)(s2 + (long)row * str2 + (k0 - ksplit)) + cb;
    cp16(sdst + r * 128 + (cb ^ ((r & 7) << 4)), src);
}

__device__ __forceinline__ void load_b_tile(uint32_t sdst, const __half* w,
                                            int K, int k0, int nt, int t)
{
#pragma unroll
    for (int i = 0; i < 4; i++) {
        int idx = i * 256 + t;
        int r = idx >> 3;
        int cb = (idx & 7) << 4;
        cp16(sdst + r * 128 + (cb ^ ((r & 7) << 4)),
             (const char*)(w + (long)(nt * 128 + r) * K + k0) + cb);
    }
}

__device__ __forceinline__ void gemm_cell_phase(uint32_t base, char* dbuf,
    const __half* A1, int str1, int ksplit,
    const __half* A2, int str2,
    const __half* W, int K,
    const float* __restrict__ bg,
    float* __restrict__ cst, __half* __restrict__ hh,
    float* __restrict__ hf, int mt, int nt)
{
    const int t = threadIdx.x;
    const int lane = t & 31, wid = t >> 5;
    const int wk = wid >> 3;            // K-group 0/1
    const int wid2 = wid & 7;
    const int wm = wid2 >> 2, wn = wid2 & 3;
    const int nch = K >> 6;
    const int halfn = nch >> 1;

    // loader mapping: lower 256 threads load group 0's chunk, upper group 1's
    const int lt = t & 255;
    const int lg = t >> 8;

    float acc[4][4];
#pragma unroll
    for (int j = 0; j < 4; j++)
#pragma unroll
        for (int v = 0; v < 4; v++) acc[j][v] = 0.f;

    const int rA = wm * 16 + ((lane >> 3) & 1) * 8 + (lane & 7);
    const int cA = (lane >> 4) * 16;
    const int gB = lane >> 3;
    const int rBb = (gB >> 1) * 8 + (lane & 7);
    const int cB = (gB & 1) * 16;

    // prologue: iteration 0 for both groups (each thread loads its lg's chunk)
    {
        uint32_t sb = base + (uint32_t)(lg * 2) * STAGE;
        int k0 = lg * halfn * 64;
        load_a_tile(sb, A1, str1, ksplit, A2, str2, k0, mt, lt);
        load_b_tile(sb + 4096, W, K, k0, nt, lt);
        CP_COMMIT();
    }

    for (int i = 0; i < halfn; i++) {
        if (i + 1 < halfn) {
            uint32_t sb = base + (uint32_t)(lg * 2 + ((i + 1) & 1)) * STAGE;
            int k0 = (lg * halfn + i + 1) * 64;
            load_a_tile(sb, A1, str1, ksplit, A2, str2, k0, mt, lt);
            load_b_tile(sb + 4096, W, K, k0, nt, lt);
            CP_COMMIT();
            asm volatile("cp.async.wait_group 1;" ::: "memory");
        } else {
            asm volatile("cp.async.wait_group 0;" ::: "memory");
        }
        __syncthreads();

        uint32_t bb = base + (uint32_t)(wk * 2 + (i & 1)) * STAGE;
#pragma unroll
        for (int kk = 0; kk < 4; kk++) {
            uint32_t ah[4], bh[2][4];
            {
                uint32_t offA = (uint32_t)(rA * 128 + ((kk * 32 + cA) ^ ((rA & 7) << 4)));
                LDSM4(ah, bb + offA);
            }
#pragma unroll
            for (int jj = 0; jj < 2; jj++) {
                int r = wn * 32 + jj * 16 + rBb;
                uint32_t offB = (uint32_t)(r * 128 + ((kk * 32 + cB) ^ ((r & 7) << 4)));
                LDSM4(bh[jj], bb + 4096 + offB);
            }
#pragma unroll
            for (int j = 0; j < 4; j++) {
                const uint32_t* bj = &bh[j >> 1][(j & 1) * 2];
                mma16816(acc[j], ah, bj);
            }
        }
        __syncthreads();
    }

    // Cross-group reduction: group 1 stores, group 0 adds + epilogue.
    // Layout: red[(j*4+v)*256 + wid2*32 + lane] — lane-contiguous, no conflicts.
    float* red = reinterpret_cast<float*>(dbuf);
    if (wk == 1) {
        int o = wid2 * 32 + lane;
#pragma unroll
        for (int j = 0; j < 4; j++)
#pragma unroll
            for (int v = 0; v < 4; v++) red[(j * 4 + v) * 256 + o] = acc[j][v];
    }
    __syncthreads();
    if (wk == 0) {
        int o = wid2 * 32 + lane;
#pragma unroll
        for (int j = 0; j < 4; j++)
#pragma unroll
            for (int v = 0; v < 4; v++) acc[j][v] += red[(j * 4 + v) * 256 + o];

        // Epilogue: LSTM cell from fragments. thread owns (b0,b0+8) x (h, h+1).
        const int b0 = mt * 32 + wm * 16 + (lane >> 2);
        const int h0i = (nt * 4 + wn) * 8 + 2 * (lane & 3);
        const int pcb = nt * 128 + wn * 32 + 2 * (lane & 3);
        float bi[4][2];
#pragma unroll
        for (int j = 0; j < 4; j++) {
            bi[j][0] = bg[pcb + j * 8];
            bi[j][1] = bg[pcb + j * 8 + 1];
        }
#pragma unroll
        for (int half = 0; half < 2; half++) {
            int b = b0 + half * 8;
            float hn[2];
#pragma unroll
            for (int u = 0; u < 2; u++) {
                int v = half * 2 + u;
                float iv = acc[0][v] + bi[0][u];
                float fv = acc[1][v] + bi[1][u];
                float gv = acc[2][v] + bi[2][u];
                float ov = acc[3][v] + bi[3][u];
                long ci = (long)b * 512 + h0i + u;
                float cn = sigf(fv) * cst[ci] + sigf(iv) * tanhf(gv);
                cst[ci] = cn;
                hn[u] = sigf(ov) * tanhf(cn);
            }
            long hi = (long)b * 512 + h0i;
            *reinterpret_cast<__half2*>(hh + hi) =
                __half2(__float2half_rn(hn[0]), __float2half_rn(hn[1]));
            if (hf) *reinterpret_cast<float2*>(hf + hi) = make_float2(hn[0], hn[1]);
        }
    }
    // grid_sync() after this function provides the barrier before smem reuse.
}

__global__ __launch_bounds__(512, 1) void decode_loop(
    const float* __restrict__ node, const float* __restrict__ Wo,
    const float* __restrict__ bo, float* __restrict__ out)
{
    extern __shared__ char dsm[];
    uint32_t base = (smem_u32(dsm) + 1023) & ~1023u;
    char* dbuf = dsm + (base - smem_u32(dsm));
    __shared__ float s_h1[1024];
    __shared__ float s_x[256], s_d[256];
    __shared__ int   s_i[256];

    const int t = threadIdx.x;
    const int bid = blockIdx.x;
    const int mt = bid >> 4, nt = bid & 15;
    const int q = t >> 7, n = t & 127;     // tail: q in 0..3, active q<2
    const bool act = q < 2;

    for (int s = 0; s < NNODES; s++) {
        const int cur = s & 1, prev = cur ^ 1;

        // Phase A: gates0 = [dec|h0] @ W0p -> cell0 -> H0[cur]
        gemm_cell_phase(base, dbuf,
            g_DEC[prev], 128, 128,
            g_H0[prev],  512,
            g_W0, 640, g_bg0,
            g_c0, g_H0[cur], nullptr, mt, nt);
        grid_sync();

        // Phase B: gates1 = [h0_new|h1_prev] @ W1p -> cell1 -> H1[cur] + h1f
        gemm_cell_phase(base, dbuf,
            g_H0[cur], 512, 512,
            g_H1[prev], 512,
            g_W1, 1024, g_bg1,
            g_c1, g_H1[cur], g_h1f, mt, nt);
        grid_sync();

        // Tail: projection + masked argmin + scatter + dec feedback (2 batches/CTA)
        {
            const int b = bid * 2 + q;
            if (act) {
#pragma unroll
                for (int j = 0; j < 4; j++)
                    s_h1[q * 512 + n + j * 128] = g_h1f[(long)b * 512 + n + j * 128];
            }
            __syncthreads();
            if (act) {
                float accp = bo[n];
                const float4* wr = reinterpret_cast<const float4*>(Wo + (long)n * 512);
                const float4* hv = reinterpret_cast<const float4*>(s_h1 + q * 512);
#pragma unroll 4
                for (int kq = 0; kq < 128; kq++) {
                    float4 w = wr[kq], h4 = hv[kq];
                    accp = fmaf(w.x, h4.x, accp); accp = fmaf(w.y, h4.y, accp);
                    accp = fmaf(w.z, h4.z, accp); accp = fmaf(w.w, h4.w, accp);
                }
                s_x[q * 128 + n] = accp;
            }
            __syncthreads();
            if (act) {
                float dist = 3.4e38f;
                if (!g_used[b * 128 + n]) {
                    const float* nd = node + ((long)b * 128 + n) * 128;
                    const float* xsb = s_x + q * 128;
                    float sum = 0.f;
#pragma unroll 8
                    for (int d = 0; d < 128; d++) {
                        float df = xsb[d] - nd[d];
                        sum = fmaf(df, df, sum);
                    }
                    dist = sum;
                }
                s_d[q * 128 + n] = dist;
                s_i[q * 128 + n] = n;
            }
            __syncthreads();
#pragma unroll
            for (int st_ = 64; st_ > 0; st_ >>= 1) {
                if (act && n < st_) {
                    float ov = s_d[q * 128 + n + st_]; int oi = s_i[q * 128 + n + st_];
                    if (ov < s_d[q * 128 + n] ||
                        (ov == s_d[q * 128 + n] && oi < s_i[q * 128 + n])) {
                        s_d[q * 128 + n] = ov; s_i[q * 128 + n] = oi;
                    }
                }
                __syncthreads();
            }
            if (act) {
                int idx = s_i[q * 128];
                if (n == 0) g_used[b * 128 + idx] = 1;
                float xv = s_x[q * 128 + n];
                out[((long)b * 128 + idx) * 128 + n] = xv;
                g_DEC[cur][b * 128 + n] = __float2half_rn(xv);
            }
        }
        grid_sync();
    }
}

// ============================================================================
// Launch
// ============================================================================
extern "C" void kernel_launch(void* const* d_in, const int* in_sizes, int n_in,
                              void* d_out, int out_size)
{
    const float* emb  = (const float*)d_in[0];
    const float* node = (const float*)d_in[1];
    const float* W1   = (const float*)d_in[2];
    const float* b1   = (const float*)d_in[3];
    const float* W2   = (const float*)d_in[4];
    const float* b2   = (const float*)d_in[5];
    const float* Wih0 = (const float*)d_in[6];
    const float* Whh0 = (const float*)d_in[7];
    const float* bih0 = (const float*)d_in[8];
    const float* bhh0 = (const float*)d_in[9];
    const float* Wih1 = (const float*)d_in[10];
    const float* Whh1 = (const float*)d_in[11];
    const float* bih1 = (const float*)d_in[12];
    const float* bhh1 = (const float*)d_in[13];
    const float* Wo   = (const float*)d_in[14];
    const float* bo   = (const float*)d_in[15];
    float* out = (float*)d_out;

    cudaFuncSetAttribute(decode_loop, cudaFuncAttributeMaxDynamicSharedMemorySize, GEMM_SMEM);

    float *pW1ft, *pW2ft, *pt, *phx;
    cudaGetSymbolAddress((void**)&pW1ft, g_W1ft);
    cudaGetSymbolAddress((void**)&pW2ft, g_W2ft);
    cudaGetSymbolAddress((void**)&pt,    g_t);
    cudaGetSymbolAddress((void**)&phx,   g_hx);

    prep_weights<<<2048, 256>>>(Wih0, Whh0, bih0, bhh0, Wih1, Whh1, bih1, bhh1, W1, W2);
    sgemm_bias<<<dim3(512 / TBN, BB / TBM), 256>>>(emb, pW1ft, b1, pt, BB, 512, 512, 512, 1);
    sgemm_bias<<<dim3(1024 / TBN, BB / TBM), 256>>>(pt, pW2ft, b2, phx, BB, 1024, 512, 512, 0);
    init_state<<<(BB * HH) / 256, 256>>>();

    decode_loop<<<NCTA, 512, GEMM_SMEM>>>(node, Wo, bo, out);
}

// round 16
// speedup vs baseline: 1.3160x; 1.0226x over previous
#include <cuda_runtime.h>
#include <cuda_fp16.h>
#include <math.h>
#include <stdint.h>

#define BB 256
#define HH 512
#define NNODES 128
#define NCTA 128
#define NCHA 10     // phase A chunks ([dec 2 | h0 8])
#define NCHB 16     // phase B chunks ([h0 8 | h1 8])

// ============================================================================
// PTX helpers. cp.async.bulk + mbarrier are plain sm_90 PTX (not 'a'-gated) —
// verified: R14 compiled and ran on this harness.
// ============================================================================
__device__ __forceinline__ uint32_t smem_u32(const void* p) {
    uint32_t a;
    asm("{ .reg .u64 t; cvta.to.shared.u64 t, %1; cvt.u32.u64 %0, t; }" : "=r"(a) : "l"(p));
    return a;
}
#define LDSM4(r, a) asm volatile("ldmatrix.sync.aligned.m8n8.x4.shared.b16 {%0,%1,%2,%3}, [%4];" \
    : "=r"((r)[0]), "=r"((r)[1]), "=r"((r)[2]), "=r"((r)[3]) : "r"(a))

__device__ __forceinline__ void mma16816(float* c, const uint32_t* a, const uint32_t* b) {
    asm volatile("mma.sync.aligned.m16n8k16.row.col.f32.f16.f16.f32 "
                 "{%0,%1,%2,%3}, {%4,%5,%6,%7}, {%8,%9}, {%0,%1,%2,%3};"
                 : "+f"(c[0]), "+f"(c[1]), "+f"(c[2]), "+f"(c[3])
                 : "r"(a[0]), "r"(a[1]), "r"(a[2]), "r"(a[3]), "r"(b[0]), "r"(b[1]));
}

#define MBARRIER_INIT(addr, cnt) \
    asm volatile("mbarrier.init.shared.b64 [%0], %1;" :: "r"((uint32_t)(addr)), "r"((uint32_t)(cnt)) : "memory")
#define MBAR_EXPECT(addr, tx) \
    asm volatile("mbarrier.arrive.expect_tx.shared.b64 _, [%0], %1;" :: "r"((uint32_t)(addr)), "r"((uint32_t)(tx)) : "memory")
#define BULK_CP(dst, src, sz, mbar) \
    asm volatile("cp.async.bulk.shared::cluster.global.mbarrier::complete_tx::bytes [%0], [%1], %2, [%3];" \
                 :: "r"((uint32_t)(dst)), "l"((const void*)(src)), "r"((uint32_t)(sz)), "r"((uint32_t)(mbar)) : "memory")
#define MBAR_WAIT(addr, ph) do { \
    uint32_t _done = 0; \
    while (!_done) { \
        asm volatile("{\n\t.reg .pred p;\n\t" \
            "mbarrier.try_wait.parity.shared.b64 p, [%1], %2;\n\t" \
            "selp.b32 %0, 1, 0, p;\n\t}" \
            : "=r"(_done) : "r"((uint32_t)(addr)), "r"((uint32_t)(ph)) : "memory"); \
    } \
} while (0)

// ============================================================================
// Device globals. Weights + activations stored PRE-SWIZZLED, chunk-blocked:
// element (row r, within-chunk col kin) lives at half-offset
//   swzo(r,kin) = r*64 + (((kin>>3)*16 ^ ((r&7)<<4))>>1) + (kin&7)
// inside its chunk block, so a LINEAR bulk copy reproduces the exact smem
// image the LDSMs of the 6206us kernel expect.
// ============================================================================
__device__ __align__(16) __half g_W0s[16 * NCHA * 8192];  // per nt: 10 chunks x 16KB
__device__ __align__(16) __half g_W1s[16 * NCHB * 8192];  // per nt: 16 chunks x 16KB
__device__ __align__(16) __half g_Aa[2][8][NCHA * 2048];  // [dec|h0] per mt, 10 x 4KB
__device__ __align__(16) __half g_Ab[2][8][NCHB * 2048];  // [h0|h1] per mt, 16 x 4KB
__device__ __align__(16) float g_W1ft[512 * 512], g_W2ft[512 * 1024];
__device__ __align__(16) float g_bg0[2048], g_bg1[2048];
__device__ __align__(16) float g_c0[BB * HH], g_c1[BB * HH], g_h1f[BB * HH];
__device__ __align__(16) float g_t[BB * 512], g_hx[BB * 1024];
__device__ unsigned char g_used[BB * NNODES];

// grid barrier state (zero-initialized at module load; self-consistent across replays)
__device__ unsigned g_cnt;
__device__ volatile unsigned g_gen;

__device__ __forceinline__ void grid_sync() {
    __syncthreads();
    if (threadIdx.x == 0) {
        __threadfence();
        unsigned gen = g_gen;
        if (atomicAdd(&g_cnt, 1u) == NCTA - 1) {
            atomicExch(&g_cnt, 0u);
            __threadfence();
            g_gen = gen + 1;
        } else {
            while (g_gen == gen) { __nanosleep(32); }
        }
        __threadfence();
    }
    __syncthreads();
}

__device__ __forceinline__ float sigf(float v) { return 1.f / (1.f + expf(-v)); }

// swizzled offset (half units) for element (row r, within-chunk col kin)
__device__ __forceinline__ int swzo(int r, int kin) {
    return r * 64 + ((((kin >> 3) * 16) ^ ((r & 7) << 4)) >> 1) + (kin & 7);
}

// ============================================================================
// Weight prep: packed column layout pc = G*32 + gate*8 + u (same as 6206),
// written into the pre-swizzled chunk-blocked global image.
// FIX vs R14: chunk base is (idx)*8192 + swzo(rr,kin) — swzo already
// contains the rr*64 row offset (it was double-counted before).
// ============================================================================
__global__ void prep_weights(const float* __restrict__ Wih0, const float* __restrict__ Whh0,
                             const float* __restrict__ bih0, const float* __restrict__ bhh0,
                             const float* __restrict__ Wih1, const float* __restrict__ Whh1,
                             const float* __restrict__ bih1, const float* __restrict__ bhh1,
                             const float* __restrict__ W1,   const float* __restrict__ W2)
{
    const long S0 = 2048L * 640;
    const long S1 = S0 + 2048L * 1024;
    const long S2 = S1 + 512L * 512;
    const long S3 = S2 + 512L * 1024;
    const long S4 = S3 + 2048;
    const long S5 = S4 + 2048;
    long stride = (long)gridDim.x * blockDim.x;
    for (long i = (long)blockIdx.x * blockDim.x + threadIdx.x; i < S5; i += stride) {
        if (i < S0) {
            long r = i; int pc = (int)(r / 640), k = (int)(r % 640);
            int n = ((pc >> 3) & 3) * 512 + (pc >> 5) * 8 + (pc & 7);
            float w = (k < 128) ? Wih0[(long)n * 128 + k] : Whh0[(long)n * 512 + (k - 128)];
            int nt = pc >> 7, rr = pc & 127, c = k >> 6, kin = k & 63;
            g_W0s[(long)(nt * NCHA + c) * 8192 + swzo(rr, kin)] = __float2half_rn(w);
        } else if (i < S1) {
            long r = i - S0; int pc = (int)(r / 1024), k = (int)(r % 1024);
            int n = ((pc >> 3) & 3) * 512 + (pc >> 5) * 8 + (pc & 7);
            float w = (k < 512) ? Wih1[(long)n * 512 + k] : Whh1[(long)n * 512 + (k - 512)];
            int nt = pc >> 7, rr = pc & 127, c = k >> 6, kin = k & 63;
            g_W1s[(long)(nt * NCHB + c) * 8192 + swzo(rr, kin)] = __float2half_rn(w);
        } else if (i < S2) {
            long r = i - S1; int k = (int)(r / 512), j = (int)(r % 512);
            g_W1ft[r] = W1[(long)j * 512 + k];
        } else if (i < S3) {
            long r = i - S2; int k = (int)(r / 1024), j = (int)(r % 1024);
            g_W2ft[r] = W2[(long)j * 512 + k];
        } else if (i < S4) {
            int pc = (int)(i - S3);
            int n = ((pc >> 3) & 3) * 512 + (pc >> 5) * 8 + (pc & 7);
            g_bg0[pc] = bih0[n] + bhh0[n];
        } else {
            int pc = (int)(i - S4);
            int n = ((pc >> 3) & 3) * 512 + (pc >> 5) * 8 + (pc & 7);
            g_bg1[pc] = bih1[n] + bhh1[n];
        }
    }
}

// ============================================================================
// State init into swizzled activation blocks (index 1 = "prev" for step 0)
// ============================================================================
__global__ void init_state()
{
    int i = blockIdx.x * blockDim.x + threadIdx.x;
    if (i >= BB * HH) return;
    int b = i >> 9, h = i & 511;
    int mt = b >> 5, rb = b & 31;
    int chunk = h >> 6, hin = h & 63;
    int ao = swzo(rb, hin);
    g_c0[i] = 0.f;
    g_c1[i] = 0.f;
    __half h0v = __float2half_rn(g_hx[b * 1024 + h]);
    __half h1v = __float2half_rn(g_hx[b * 1024 + 512 + h]);
    g_Aa[1][mt][(2 + chunk) * 2048 + ao] = h0v;
    g_Ab[1][mt][chunk * 2048 + ao]       = h0v;
    g_Ab[1][mt][(8 + chunk) * 2048 + ao] = h1v;
    if (h < 128) {
        g_Aa[1][mt][chunk * 2048 + ao] = __float2half_rn(0.f);  // dec = 0
        g_used[b * 128 + h] = 0;
    }
}

// ============================================================================
// fp32 SGEMM for the one-time FNN init
// ============================================================================
#define TBM 64
#define TBN 64
#define TBK 16
__global__ __launch_bounds__(256) void sgemm_bias(
    const float* __restrict__ A, const float* __restrict__ Bm,
    const float* __restrict__ bias, float* __restrict__ C,
    int M, int N, int K, int lda, int relu)
{
    __shared__ __align__(16) float As[TBK][TBM + 4];
    __shared__ __align__(16) float Bs[TBK][TBN + 4];
    const int t = threadIdx.x;
    const int bM = blockIdx.y * TBM, bN = blockIdx.x * TBN;
    const int tx = t & 15, ty = t >> 4;
    const int arow = t >> 2, ak = (t & 3) * 4;
    const int bk = t >> 4, bn = (t & 15) * 4;
    float acc[4][4];
#pragma unroll
    for (int i = 0; i < 4; i++)
#pragma unroll
        for (int j = 0; j < 4; j++) acc[i][j] = 0.f;
    for (int k0 = 0; k0 < K; k0 += TBK) {
        float4 a4 = *reinterpret_cast<const float4*>(A + (long)(bM + arow) * lda + k0 + ak);
        As[ak + 0][arow] = a4.x; As[ak + 1][arow] = a4.y;
        As[ak + 2][arow] = a4.z; As[ak + 3][arow] = a4.w;
        *reinterpret_cast<float4*>(&Bs[bk][bn]) =
            *reinterpret_cast<const float4*>(Bm + (long)(k0 + bk) * N + bN + bn);
        __syncthreads();
#pragma unroll
        for (int kk = 0; kk < TBK; kk++) {
            float4 av = *reinterpret_cast<const float4*>(&As[kk][ty * 4]);
            float4 bv = *reinterpret_cast<const float4*>(&Bs[kk][tx * 4]);
            float a[4] = {av.x, av.y, av.z, av.w};
            float b[4] = {bv.x, bv.y, bv.z, bv.w};
#pragma unroll
            for (int i = 0; i < 4; i++)
#pragma unroll
                for (int j = 0; j < 4; j++) acc[i][j] = fmaf(a[i], b[j], acc[i][j]);
        }
        __syncthreads();
    }
    float4 bv = *reinterpret_cast<const float4*>(bias + bN + tx * 4);
    float bb[4] = {bv.x, bv.y, bv.z, bv.w};
#pragma unroll
    for (int i = 0; i < 4; i++) {
        float4 o;
        o.x = acc[i][0] + bb[0]; o.y = acc[i][1] + bb[1];
        o.z = acc[i][2] + bb[2]; o.w = acc[i][3] + bb[3];
        if (relu) { o.x = fmaxf(o.x, 0.f); o.y = fmaxf(o.y, 0.f);
                    o.z = fmaxf(o.z, 0.f); o.w = fmaxf(o.w, 0.f); }
        *reinterpret_cast<float4*>(C + (long)(bM + ty * 4 + i) * N + bN + tx * 4) = o;
    }
}

// ============================================================================
// Persistent decode loop: 128 CTAs x 256 threads (8 warps, warp grid 2x4,
// warp tile 16x32). CTA tile 32(M)x128(N). KC=64 double-buffered via
// cp.async.bulk (ONE instruction per tile) + mbarrier expect_tx — removes
// the 1280-op/chunk LDGSTS issue bottleneck. Math identical to 6206 kernel.
// stage = A 4K | B 16K = 20K; x2 = 40K dynamic smem.
// ============================================================================
#define STAGE 20480
#define GEMM_SMEM (2 * STAGE + 1024)

__device__ __forceinline__ void gemm_cell_phase(uint32_t base,
    uint32_t mb0, uint32_t mb1, unsigned& p0, unsigned& p1,
    const __half* __restrict__ pA1, const __half* __restrict__ pA2, int csplit,
    const __half* __restrict__ Wb, int nch,
    const float* __restrict__ bg,
    float* __restrict__ cst,
    __half* __restrict__ d1, int c1off,
    __half* __restrict__ d2, int c2off,
    float* __restrict__ hf, int mt, int nt)
{
    const int t = threadIdx.x;
    const int lane = t & 31, wid = t >> 5;
    const int wm = wid >> 2, wn = wid & 3;

    float acc[4][4];
#pragma unroll
    for (int j = 0; j < 4; j++)
#pragma unroll
        for (int v = 0; v < 4; v++) acc[j][v] = 0.f;

    const int rA = wm * 16 + ((lane >> 3) & 1) * 8 + (lane & 7);
    const int cA = (lane >> 4) * 16;
    const int gB = lane >> 3;
    const int rBb = (gB >> 1) * 8 + (lane & 7);
    const int cB = (gB & 1) * 16;

    // producer: one bulk copy per tile, mbarrier transaction-tracked
    auto issue = [&](int c) {
        uint32_t sb = base + (uint32_t)(c & 1) * STAGE;
        uint32_t mb = (c & 1) ? mb1 : mb0;
        MBAR_EXPECT(mb, 20480);
        const __half* as = ((c < csplit) ? pA1 : pA2) + (long)c * 2048;
        BULK_CP(sb, as, 4096, mb);
        BULK_CP(sb + 4096, Wb + (long)c * 8192, 16384, mb);
    };

    if (t == 0) { issue(0); issue(1); }

    for (int c = 0; c < nch; c++) {
        uint32_t mb = (c & 1) ? mb1 : mb0;
        unsigned ph = (c & 1) ? p1 : p0;
        MBAR_WAIT(mb, ph);
        if (c & 1) p1 ^= 1; else p0 ^= 1;

        uint32_t bb = base + (uint32_t)(c & 1) * STAGE;
#pragma unroll
        for (int kk = 0; kk < 4; kk++) {
            uint32_t ah[4], bh[2][4];
            {
                uint32_t offA = (uint32_t)(rA * 128 + ((kk * 32 + cA) ^ ((rA & 7) << 4)));
                LDSM4(ah, bb + offA);
            }
#pragma unroll
            for (int jj = 0; jj < 2; jj++) {
                int r = wn * 32 + jj * 16 + rBb;
                uint32_t offB = (uint32_t)(r * 128 + ((kk * 32 + cB) ^ ((r & 7) << 4)));
                LDSM4(bh[jj], bb + 4096 + offB);
            }
#pragma unroll
            for (int j = 0; j < 4; j++) {
                const uint32_t* bj = &bh[j >> 1][(j & 1) * 2];
                mma16816(acc[j], ah, bj);
            }
        }
        __syncthreads();            // all warps done reading stage (c&1)
        if (t == 0 && c + 2 < nch) issue(c + 2);
    }

    // Epilogue: LSTM cell from fragments; write h into swizzled global blocks.
    const int b0 = mt * 32 + wm * 16 + (lane >> 2);
    const int h0i = (nt * 4 + wn) * 8 + 2 * (lane & 3);
    const int pcb = nt * 128 + wn * 32 + 2 * (lane & 3);
    const int chunkH = h0i >> 6, hin = h0i & 63;
    float bi[4][2];
#pragma unroll
    for (int j = 0; j < 4; j++) {
        bi[j][0] = bg[pcb + j * 8];
        bi[j][1] = bg[pcb + j * 8 + 1];
    }
#pragma unroll
    for (int half = 0; half < 2; half++) {
        int b = b0 + half * 8;
        int rb = b - mt * 32;
        float hn[2];
#pragma unroll
        for (int u = 0; u < 2; u++) {
            int v = half * 2 + u;
            float iv = acc[0][v] + bi[0][u];
            float fv = acc[1][v] + bi[1][u];
            float gv = acc[2][v] + bi[2][u];
            float ov = acc[3][v] + bi[3][u];
            long ci = (long)b * 512 + h0i + u;
            float cn = sigf(fv) * cst[ci] + sigf(iv) * tanhf(gv);
            cst[ci] = cn;
            hn[u] = sigf(ov) * tanhf(cn);
        }
        __half2 hv = __half2(__float2half_rn(hn[0]), __float2half_rn(hn[1]));
        int ao = swzo(rb, hin);
        *reinterpret_cast<__half2*>(d1 + (long)(c1off + chunkH) * 2048 + ao) = hv;
        if (d2) *reinterpret_cast<__half2*>(d2 + (long)(c2off + chunkH) * 2048 + ao) = hv;
        if (hf) *reinterpret_cast<float2*>(hf + (long)b * 512 + h0i) = make_float2(hn[0], hn[1]);
    }
}

__global__ __launch_bounds__(256, 1) void decode_loop(
    const float* __restrict__ node, const float* __restrict__ Wo,
    const float* __restrict__ bo, float* __restrict__ out)
{
    extern __shared__ char dsm[];
    uint32_t base = (smem_u32(dsm) + 1023) & ~1023u;
    __shared__ __align__(8) uint64_t s_mb[2];
    __shared__ float s_h1[1024];
    __shared__ float s_x[256], s_d[256];
    __shared__ int   s_i[256];

    const int t = threadIdx.x;
    const int bid = blockIdx.x;
    const int mt = bid >> 4, nt = bid & 15;
    const int q = t >> 7, n = t & 127;   // tail: 2 batches per CTA

    uint32_t mb0 = smem_u32(&s_mb[0]);
    uint32_t mb1 = smem_u32(&s_mb[1]);
    if (t == 0) {
        MBARRIER_INIT(mb0, 1);
        MBARRIER_INIT(mb1, 1);
    }
    __syncthreads();
    unsigned p0 = 0, p1 = 0;

    for (int s = 0; s < NNODES; s++) {
        const int cur = s & 1, prev = cur ^ 1;

        // Phase A: [dec|h0](prev) @ W0 -> cell0 -> h0 into Aa[cur]+2, Ab[cur]+0
        gemm_cell_phase(base, mb0, mb1, p0, p1,
            g_Aa[prev][mt], g_Aa[prev][mt], NCHA,
            g_W0s + (long)nt * NCHA * 8192, NCHA, g_bg0,
            g_c0,
            g_Aa[cur][mt], 2, g_Ab[cur][mt], 0,
            nullptr, mt, nt);
        grid_sync();

        // Phase B: [h0(cur) | h1(prev)] @ W1 -> cell1 -> h1 into Ab[cur]+8, h1f
        gemm_cell_phase(base, mb0, mb1, p0, p1,
            g_Ab[cur][mt], g_Ab[prev][mt], 8,
            g_W1s + (long)nt * NCHB * 8192, NCHB, g_bg1,
            g_c1,
            g_Ab[cur][mt], 8, nullptr, 0,
            g_h1f, mt, nt);
        grid_sync();

        // Tail: projection + masked argmin + scatter + dec feedback
        {
            const int b = bid * 2 + q;
#pragma unroll
            for (int j = 0; j < 4; j++)
                s_h1[q * 512 + n + j * 128] = g_h1f[(long)b * 512 + n + j * 128];
            __syncthreads();
            float accp = bo[n];
            const float4* wr = reinterpret_cast<const float4*>(Wo + (long)n * 512);
            const float4* hv = reinterpret_cast<const float4*>(s_h1 + q * 512);
#pragma unroll 4
            for (int kq = 0; kq < 128; kq++) {
                float4 w = wr[kq], h4 = hv[kq];
                accp = fmaf(w.x, h4.x, accp); accp = fmaf(w.y, h4.y, accp);
                accp = fmaf(w.z, h4.z, accp); accp = fmaf(w.w, h4.w, accp);
            }
            s_x[q * 128 + n] = accp;
            __syncthreads();
            float dist = 3.4e38f;
            if (!g_used[b * 128 + n]) {
                const float* nd = node + ((long)b * 128 + n) * 128;
                const float* xsb = s_x + q * 128;
                float sum = 0.f;
#pragma unroll 8
                for (int d = 0; d < 128; d++) {
                    float df = xsb[d] - nd[d];
                    sum = fmaf(df, df, sum);
                }
                dist = sum;
            }
            s_d[q * 128 + n] = dist;
            s_i[q * 128 + n] = n;
            __syncthreads();
#pragma unroll
            for (int st_ = 64; st_ > 0; st_ >>= 1) {
                if (n < st_) {
                    float ov = s_d[q * 128 + n + st_]; int oi = s_i[q * 128 + n + st_];
                    if (ov < s_d[q * 128 + n] ||
                        (ov == s_d[q * 128 + n] && oi < s_i[q * 128 + n])) {
                        s_d[q * 128 + n] = ov; s_i[q * 128 + n] = oi;
                    }
                }
                __syncthreads();
            }
            int idx = s_i[q * 128];
            if (n == 0) g_used[b * 128 + idx] = 1;
            float xv = s_x[q * 128 + n];
            out[((long)b * 128 + idx) * 128 + n] = xv;
            // dec feedback into swizzled Aa[cur] chunks 0-1
            int mtb = b >> 5, rb = b & 31;
            g_Aa[cur][mtb][(n >> 6) * 2048 + swzo(rb, n & 63)] = __float2half_rn(xv);
        }
        grid_sync();
    }
}

// ============================================================================
// Launch
// ============================================================================
extern "C" void kernel_launch(void* const* d_in, const int* in_sizes, int n_in,
                              void* d_out, int out_size)
{
    const float* emb  = (const float*)d_in[0];
    const float* node = (const float*)d_in[1];
    const float* W1   = (const float*)d_in[2];
    const float* b1   = (const float*)d_in[3];
    const float* W2   = (const float*)d_in[4];
    const float* b2   = (const float*)d_in[5];
    const float* Wih0 = (const float*)d_in[6];
    const float* Whh0 = (const float*)d_in[7];
    const float* bih0 = (const float*)d_in[8];
    const float* bhh0 = (const float*)d_in[9];
    const float* Wih1 = (const float*)d_in[10];
    const float* Whh1 = (const float*)d_in[11];
    const float* bih1 = (const float*)d_in[12];
    const float* bhh1 = (const float*)d_in[13];
    const float* Wo   = (const float*)d_in[14];
    const float* bo   = (const float*)d_in[15];
    float* out = (float*)d_out;

    cudaFuncSetAttribute(decode_loop, cudaFuncAttributeMaxDynamicSharedMemorySize, GEMM_SMEM);

    float *pW1ft, *pW2ft, *pt, *phx;
    cudaGetSymbolAddress((void**)&pW1ft, g_W1ft);
    cudaGetSymbolAddress((void**)&pW2ft, g_W2ft);
    cudaGetSymbolAddress((void**)&pt,    g_t);
    cudaGetSymbolAddress((void**)&phx,   g_hx);

    prep_weights<<<2048, 256>>>(Wih0, Whh0, bih0, bhh0, Wih1, Whh1, bih1, bhh1, W1, W2);
    sgemm_bias<<<dim3(512 / TBN, BB / TBM), 256>>>(emb, pW1ft, b1, pt, BB, 512, 512, 512, 1);
    sgemm_bias<<<dim3(1024 / TBN, BB / TBM), 256>>>(pt, pW2ft, b2, phx, BB, 1024, 512, 512, 0);
    init_state<<<(BB * HH) / 256, 256>>>();

    decode_loop<<<NCTA, 256, GEMM_SMEM>>>(node, Wo, bo, out);
}

// round 17
// speedup vs baseline: 1.3253x; 1.0070x over previous
#include <cuda_runtime.h>
#include <cuda_fp16.h>
#include <math.h>
#include <stdint.h>

#define BB 256
#define HH 512
#define NNODES 128
#define NCTA 128
#define NCHA 10     // phase A chunks ([dec 2 | h0 8])
#define NCHB 16     // phase B chunks ([h0 8 | h1 8])

// ============================================================================
// PTX helpers. cp.async.bulk + mbarrier are plain sm_90 PTX (not 'a'-gated) —
// verified working on this harness (R14/R16).
// ============================================================================
__device__ __forceinline__ uint32_t smem_u32(const void* p) {
    uint32_t a;
    asm("{ .reg .u64 t; cvta.to.shared.u64 t, %1; cvt.u32.u64 %0, t; }" : "=r"(a) : "l"(p));
    return a;
}
#define LDSM4(r, a) asm volatile("ldmatrix.sync.aligned.m8n8.x4.shared.b16 {%0,%1,%2,%3}, [%4];" \
    : "=r"((r)[0]), "=r"((r)[1]), "=r"((r)[2]), "=r"((r)[3]) : "r"(a))

__device__ __forceinline__ void mma16816(float* c, const uint32_t* a, const uint32_t* b) {
    asm volatile("mma.sync.aligned.m16n8k16.row.col.f32.f16.f16.f32 "
                 "{%0,%1,%2,%3}, {%4,%5,%6,%7}, {%8,%9}, {%0,%1,%2,%3};"
                 : "+f"(c[0]), "+f"(c[1]), "+f"(c[2]), "+f"(c[3])
                 : "r"(a[0]), "r"(a[1]), "r"(a[2]), "r"(a[3]), "r"(b[0]), "r"(b[1]));
}

#define MBARRIER_INIT(addr, cnt) \
    asm volatile("mbarrier.init.shared.b64 [%0], %1;" :: "r"((uint32_t)(addr)), "r"((uint32_t)(cnt)) : "memory")
#define MBAR_EXPECT(addr, tx) \
    asm volatile("mbarrier.arrive.expect_tx.shared.b64 _, [%0], %1;" :: "r"((uint32_t)(addr)), "r"((uint32_t)(tx)) : "memory")
#define BULK_CP(dst, src, sz, mbar) \
    asm volatile("cp.async.bulk.shared::cluster.global.mbarrier::complete_tx::bytes [%0], [%1], %2, [%3];" \
                 :: "r"((uint32_t)(dst)), "l"((const void*)(src)), "r"((uint32_t)(sz)), "r"((uint32_t)(mbar)) : "memory")
#define MBAR_WAIT(addr, ph) do { \
    uint32_t _done = 0; \
    while (!_done) { \
        asm volatile("{\n\t.reg .pred p;\n\t" \
            "mbarrier.try_wait.parity.shared.b64 p, [%1], %2;\n\t" \
            "selp.b32 %0, 1, 0, p;\n\t}" \
            : "=r"(_done) : "r"((uint32_t)(addr)), "r"((uint32_t)(ph)) : "memory"); \
    } \
} while (0)

// ============================================================================
// Device globals. Weights + activations stored PRE-SWIZZLED, chunk-blocked:
// element (row r, within-chunk col kin) lives at half-offset
//   swzo(r,kin) = r*64 + (((kin>>3)*16 ^ ((r&7)<<4))>>1) + (kin&7)
// inside its chunk block, so a LINEAR bulk copy reproduces the exact smem
// image the LDSMs of the 6206us kernel expect.
// ============================================================================
__device__ __align__(16) __half g_W0s[16 * NCHA * 8192];  // per nt: 10 chunks x 16KB
__device__ __align__(16) __half g_W1s[16 * NCHB * 8192];  // per nt: 16 chunks x 16KB
__device__ __align__(16) __half g_Aa[2][8][NCHA * 2048];  // [dec|h0] per mt, 10 x 4KB
__device__ __align__(16) __half g_Ab[2][8][NCHB * 2048];  // [h0|h1] per mt, 16 x 4KB
__device__ __align__(16) float g_W1ft[512 * 512], g_W2ft[512 * 1024];
__device__ __align__(16) float g_bg0[2048], g_bg1[2048];
__device__ __align__(16) float g_c0[BB * HH], g_c1[BB * HH], g_h1f[BB * HH];
__device__ __align__(16) float g_t[BB * 512], g_hx[BB * 1024];
__device__ unsigned char g_used[BB * NNODES];

// per-mt-group barrier state: 8 independent 16-CTA barriers, each on its own
// 128B L2 line (zero-initialized; sense-reversing, replay-safe)
struct __align__(128) GroupBar { unsigned cnt; volatile unsigned gen; unsigned pad[30]; };
__device__ GroupBar g_gb[8];

__device__ __forceinline__ void group_sync(int mt) {
    __syncthreads();
    if (threadIdx.x == 0) {
        __threadfence();
        unsigned gen = g_gb[mt].gen;
        if (atomicAdd(&g_gb[mt].cnt, 1u) == 15u) {
            atomicExch(&g_gb[mt].cnt, 0u);
            __threadfence();
            g_gb[mt].gen = gen + 1;
        } else {
            while (g_gb[mt].gen == gen) { __nanosleep(32); }
        }
        __threadfence();
    }
    __syncthreads();
}

__device__ __forceinline__ float sigf(float v) { return 1.f / (1.f + expf(-v)); }

// swizzled offset (half units) for element (row r, within-chunk col kin)
__device__ __forceinline__ int swzo(int r, int kin) {
    return r * 64 + ((((kin >> 3) * 16) ^ ((r & 7) << 4)) >> 1) + (kin & 7);
}

// ============================================================================
// Weight prep: packed column layout pc = G*32 + gate*8 + u (same as 6206),
// written into the pre-swizzled chunk-blocked global image.
// ============================================================================
__global__ void prep_weights(const float* __restrict__ Wih0, const float* __restrict__ Whh0,
                             const float* __restrict__ bih0, const float* __restrict__ bhh0,
                             const float* __restrict__ Wih1, const float* __restrict__ Whh1,
                             const float* __restrict__ bih1, const float* __restrict__ bhh1,
                             const float* __restrict__ W1,   const float* __restrict__ W2)
{
    const long S0 = 2048L * 640;
    const long S1 = S0 + 2048L * 1024;
    const long S2 = S1 + 512L * 512;
    const long S3 = S2 + 512L * 1024;
    const long S4 = S3 + 2048;
    const long S5 = S4 + 2048;
    long stride = (long)gridDim.x * blockDim.x;
    for (long i = (long)blockIdx.x * blockDim.x + threadIdx.x; i < S5; i += stride) {
        if (i < S0) {
            long r = i; int pc = (int)(r / 640), k = (int)(r % 640);
            int n = ((pc >> 3) & 3) * 512 + (pc >> 5) * 8 + (pc & 7);
            float w = (k < 128) ? Wih0[(long)n * 128 + k] : Whh0[(long)n * 512 + (k - 128)];
            int nt = pc >> 7, rr = pc & 127, c = k >> 6, kin = k & 63;
            g_W0s[(long)(nt * NCHA + c) * 8192 + swzo(rr, kin)] = __float2half_rn(w);
        } else if (i < S1) {
            long r = i - S0; int pc = (int)(r / 1024), k = (int)(r % 1024);
            int n = ((pc >> 3) & 3) * 512 + (pc >> 5) * 8 + (pc & 7);
            float w = (k < 512) ? Wih1[(long)n * 512 + k] : Whh1[(long)n * 512 + (k - 512)];
            int nt = pc >> 7, rr = pc & 127, c = k >> 6, kin = k & 63;
            g_W1s[(long)(nt * NCHB + c) * 8192 + swzo(rr, kin)] = __float2half_rn(w);
        } else if (i < S2) {
            long r = i - S1; int k = (int)(r / 512), j = (int)(r % 512);
            g_W1ft[r] = W1[(long)j * 512 + k];
        } else if (i < S3) {
            long r = i - S2; int k = (int)(r / 1024), j = (int)(r % 1024);
            g_W2ft[r] = W2[(long)j * 512 + k];
        } else if (i < S4) {
            int pc = (int)(i - S3);
            int n = ((pc >> 3) & 3) * 512 + (pc >> 5) * 8 + (pc & 7);
            g_bg0[pc] = bih0[n] + bhh0[n];
        } else {
            int pc = (int)(i - S4);
            int n = ((pc >> 3) & 3) * 512 + (pc >> 5) * 8 + (pc & 7);
            g_bg1[pc] = bih1[n] + bhh1[n];
        }
    }
}

// ============================================================================
// State init into swizzled activation blocks (index 1 = "prev" for step 0)
// ============================================================================
__global__ void init_state()
{
    int i = blockIdx.x * blockDim.x + threadIdx.x;
    if (i >= BB * HH) return;
    int b = i >> 9, h = i & 511;
    int mt = b >> 5, rb = b & 31;
    int chunk = h >> 6, hin = h & 63;
    int ao = swzo(rb, hin);
    g_c0[i] = 0.f;
    g_c1[i] = 0.f;
    __half h0v = __float2half_rn(g_hx[b * 1024 + h]);
    __half h1v = __float2half_rn(g_hx[b * 1024 + 512 + h]);
    g_Aa[1][mt][(2 + chunk) * 2048 + ao] = h0v;
    g_Ab[1][mt][chunk * 2048 + ao]       = h0v;
    g_Ab[1][mt][(8 + chunk) * 2048 + ao] = h1v;
    if (h < 128) {
        g_Aa[1][mt][chunk * 2048 + ao] = __float2half_rn(0.f);  // dec = 0
        g_used[b * 128 + h] = 0;
    }
}

// ============================================================================
// fp32 SGEMM for the one-time FNN init
// ============================================================================
#define TBM 64
#define TBN 64
#define TBK 16
__global__ __launch_bounds__(256) void sgemm_bias(
    const float* __restrict__ A, const float* __restrict__ Bm,
    const float* __restrict__ bias, float* __restrict__ C,
    int M, int N, int K, int lda, int relu)
{
    __shared__ __align__(16) float As[TBK][TBM + 4];
    __shared__ __align__(16) float Bs[TBK][TBN + 4];
    const int t = threadIdx.x;
    const int bM = blockIdx.y * TBM, bN = blockIdx.x * TBN;
    const int tx = t & 15, ty = t >> 4;
    const int arow = t >> 2, ak = (t & 3) * 4;
    const int bk = t >> 4, bn = (t & 15) * 4;
    float acc[4][4];
#pragma unroll
    for (int i = 0; i < 4; i++)
#pragma unroll
        for (int j = 0; j < 4; j++) acc[i][j] = 0.f;
    for (int k0 = 0; k0 < K; k0 += TBK) {
        float4 a4 = *reinterpret_cast<const float4*>(A + (long)(bM + arow) * lda + k0 + ak);
        As[ak + 0][arow] = a4.x; As[ak + 1][arow] = a4.y;
        As[ak + 2][arow] = a4.z; As[ak + 3][arow] = a4.w;
        *reinterpret_cast<float4*>(&Bs[bk][bn]) =
            *reinterpret_cast<const float4*>(Bm + (long)(k0 + bk) * N + bN + bn);
        __syncthreads();
#pragma unroll
        for (int kk = 0; kk < TBK; kk++) {
            float4 av = *reinterpret_cast<const float4*>(&As[kk][ty * 4]);
            float4 bv = *reinterpret_cast<const float4*>(&Bs[kk][tx * 4]);
            float a[4] = {av.x, av.y, av.z, av.w};
            float b[4] = {bv.x, bv.y, bv.z, bv.w};
#pragma unroll
            for (int i = 0; i < 4; i++)
#pragma unroll
                for (int j = 0; j < 4; j++) acc[i][j] = fmaf(a[i], b[j], acc[i][j]);
        }
        __syncthreads();
    }
    float4 bv = *reinterpret_cast<const float4*>(bias + bN + tx * 4);
    float bb[4] = {bv.x, bv.y, bv.z, bv.w};
#pragma unroll
    for (int i = 0; i < 4; i++) {
        float4 o;
        o.x = acc[i][0] + bb[0]; o.y = acc[i][1] + bb[1];
        o.z = acc[i][2] + bb[2]; o.w = acc[i][3] + bb[3];
        if (relu) { o.x = fmaxf(o.x, 0.f); o.y = fmaxf(o.y, 0.f);
                    o.z = fmaxf(o.z, 0.f); o.w = fmaxf(o.w, 0.f); }
        *reinterpret_cast<float4*>(C + (long)(bM + ty * 4 + i) * N + bN + tx * 4) = o;
    }
}

// ============================================================================
// Persistent decode loop: 128 CTAs x 256 threads (8 warps, warp grid 2x4,
// warp tile 16x32). CTA tile 32(M)x128(N). KC=64 double-buffered via
// cp.async.bulk + mbarrier expect_tx. Math identical to 6148us kernel.
// ONLY change vs 6148: grid barrier -> per-mt 16-CTA group barrier (the 8
// mt groups are fully independent: all state is partitioned by batch rows).
// stage = A 4K | B 16K = 20K; x2 = 40K dynamic smem.
// ============================================================================
#define STAGE 20480
#define GEMM_SMEM (2 * STAGE + 1024)

__device__ __forceinline__ void gemm_cell_phase(uint32_t base,
    uint32_t mb0, uint32_t mb1, unsigned& p0, unsigned& p1,
    const __half* __restrict__ pA1, const __half* __restrict__ pA2, int csplit,
    const __half* __restrict__ Wb, int nch,
    const float* __restrict__ bg,
    float* __restrict__ cst,
    __half* __restrict__ d1, int c1off,
    __half* __restrict__ d2, int c2off,
    float* __restrict__ hf, int mt, int nt)
{
    const int t = threadIdx.x;
    const int lane = t & 31, wid = t >> 5;
    const int wm = wid >> 2, wn = wid & 3;

    float acc[4][4];
#pragma unroll
    for (int j = 0; j < 4; j++)
#pragma unroll
        for (int v = 0; v < 4; v++) acc[j][v] = 0.f;

    const int rA = wm * 16 + ((lane >> 3) & 1) * 8 + (lane & 7);
    const int cA = (lane >> 4) * 16;
    const int gB = lane >> 3;
    const int rBb = (gB >> 1) * 8 + (lane & 7);
    const int cB = (gB & 1) * 16;

    auto issue = [&](int c) {
        uint32_t sb = base + (uint32_t)(c & 1) * STAGE;
        uint32_t mb = (c & 1) ? mb1 : mb0;
        MBAR_EXPECT(mb, 20480);
        const __half* as = ((c < csplit) ? pA1 : pA2) + (long)c * 2048;
        BULK_CP(sb, as, 4096, mb);
        BULK_CP(sb + 4096, Wb + (long)c * 8192, 16384, mb);
    };

    if (t == 0) { issue(0); issue(1); }

    for (int c = 0; c < nch; c++) {
        uint32_t mb = (c & 1) ? mb1 : mb0;
        unsigned ph = (c & 1) ? p1 : p0;
        MBAR_WAIT(mb, ph);
        if (c & 1) p1 ^= 1; else p0 ^= 1;

        uint32_t bb = base + (uint32_t)(c & 1) * STAGE;
#pragma unroll
        for (int kk = 0; kk < 4; kk++) {
            uint32_t ah[4], bh[2][4];
            {
                uint32_t offA = (uint32_t)(rA * 128 + ((kk * 32 + cA) ^ ((rA & 7) << 4)));
                LDSM4(ah, bb + offA);
            }
#pragma unroll
            for (int jj = 0; jj < 2; jj++) {
                int r = wn * 32 + jj * 16 + rBb;
                uint32_t offB = (uint32_t)(r * 128 + ((kk * 32 + cB) ^ ((r & 7) << 4)));
                LDSM4(bh[jj], bb + 4096 + offB);
            }
#pragma unroll
            for (int j = 0; j < 4; j++) {
                const uint32_t* bj = &bh[j >> 1][(j & 1) * 2];
                mma16816(acc[j], ah, bj);
            }
        }
        __syncthreads();            // all warps done reading stage (c&1)
        if (t == 0 && c + 2 < nch) issue(c + 2);
    }

    // Epilogue: LSTM cell from fragments; write h into swizzled global blocks.
    const int b0 = mt * 32 + wm * 16 + (lane >> 2);
    const int h0i = (nt * 4 + wn) * 8 + 2 * (lane & 3);
    const int pcb = nt * 128 + wn * 32 + 2 * (lane & 3);
    const int chunkH = h0i >> 6, hin = h0i & 63;
    float bi[4][2];
#pragma unroll
    for (int j = 0; j < 4; j++) {
        bi[j][0] = bg[pcb + j * 8];
        bi[j][1] = bg[pcb + j * 8 + 1];
    }
#pragma unroll
    for (int half = 0; half < 2; half++) {
        int b = b0 + half * 8;
        int rb = b - mt * 32;
        float hn[2];
#pragma unroll
        for (int u = 0; u < 2; u++) {
            int v = half * 2 + u;
            float iv = acc[0][v] + bi[0][u];
            float fv = acc[1][v] + bi[1][u];
            float gv = acc[2][v] + bi[2][u];
            float ov = acc[3][v] + bi[3][u];
            long ci = (long)b * 512 + h0i + u;
            float cn = sigf(fv) * cst[ci] + sigf(iv) * tanhf(gv);
            cst[ci] = cn;
            hn[u] = sigf(ov) * tanhf(cn);
        }
        __half2 hv = __half2(__float2half_rn(hn[0]), __float2half_rn(hn[1]));
        int ao = swzo(rb, hin);
        *reinterpret_cast<__half2*>(d1 + (long)(c1off + chunkH) * 2048 + ao) = hv;
        if (d2) *reinterpret_cast<__half2*>(d2 + (long)(c2off + chunkH) * 2048 + ao) = hv;
        if (hf) *reinterpret_cast<float2*>(hf + (long)b * 512 + h0i) = make_float2(hn[0], hn[1]);
    }
}

__global__ __launch_bounds__(256, 1) void decode_loop(
    const float* __restrict__ node, const float* __restrict__ Wo,
    const float* __restrict__ bo, float* __restrict__ out)
{
    extern __shared__ char dsm[];
    uint32_t base = (smem_u32(dsm) + 1023) & ~1023u;
    __shared__ __align__(8) uint64_t s_mb[2];
    __shared__ float s_h1[1024];
    __shared__ float s_x[256], s_d[256];
    __shared__ int   s_i[256];

    const int t = threadIdx.x;
    const int bid = blockIdx.x;
    const int mt = bid >> 4, nt = bid & 15;
    const int q = t >> 7, n = t & 127;   // tail: 2 batches per CTA

    uint32_t mb0 = smem_u32(&s_mb[0]);
    uint32_t mb1 = smem_u32(&s_mb[1]);
    if (t == 0) {
        MBARRIER_INIT(mb0, 1);
        MBARRIER_INIT(mb1, 1);
    }
    __syncthreads();
    unsigned p0 = 0, p1 = 0;

    for (int s = 0; s < NNODES; s++) {
        const int cur = s & 1, prev = cur ^ 1;

        // Phase A: [dec|h0](prev) @ W0 -> cell0 -> h0 into Aa[cur]+2, Ab[cur]+0
        gemm_cell_phase(base, mb0, mb1, p0, p1,
            g_Aa[prev][mt], g_Aa[prev][mt], NCHA,
            g_W0s + (long)nt * NCHA * 8192, NCHA, g_bg0,
            g_c0,
            g_Aa[cur][mt], 2, g_Ab[cur][mt], 0,
            nullptr, mt, nt);
        group_sync(mt);

        // Phase B: [h0(cur) | h1(prev)] @ W1 -> cell1 -> h1 into Ab[cur]+8, h1f
        gemm_cell_phase(base, mb0, mb1, p0, p1,
            g_Ab[cur][mt], g_Ab[prev][mt], 8,
            g_W1s + (long)nt * NCHB * 8192, NCHB, g_bg1,
            g_c1,
            g_Ab[cur][mt], 8, nullptr, 0,
            g_h1f, mt, nt);
        group_sync(mt);

        // Tail: projection + masked argmin + scatter + dec feedback
        {
            const int b = bid * 2 + q;
#pragma unroll
            for (int j = 0; j < 4; j++)
                s_h1[q * 512 + n + j * 128] = g_h1f[(long)b * 512 + n + j * 128];
            __syncthreads();
            float accp = bo[n];
            const float4* wr = reinterpret_cast<const float4*>(Wo + (long)n * 512);
            const float4* hv = reinterpret_cast<const float4*>(s_h1 + q * 512);
#pragma unroll 4
            for (int kq = 0; kq < 128; kq++) {
                float4 w = wr[kq], h4 = hv[kq];
                accp = fmaf(w.x, h4.x, accp); accp = fmaf(w.y, h4.y, accp);
                accp = fmaf(w.z, h4.z, accp); accp = fmaf(w.w, h4.w, accp);
            }
            s_x[q * 128 + n] = accp;
            __syncthreads();
            float dist = 3.4e38f;
            if (!g_used[b * 128 + n]) {
                const float* nd = node + ((long)b * 128 + n) * 128;
                const float* xsb = s_x + q * 128;
                float sum = 0.f;
#pragma unroll 8
                for (int d = 0; d < 128; d++) {
                    float df = xsb[d] - nd[d];
                    sum = fmaf(df, df, sum);
                }
                dist = sum;
            }
            s_d[q * 128 + n] = dist;
            s_i[q * 128 + n] = n;
            __syncthreads();
#pragma unroll
            for (int st_ = 64; st_ > 0; st_ >>= 1) {
                if (n < st_) {
                    float ov = s_d[q * 128 + n + st_]; int oi = s_i[q * 128 + n + st_];
                    if (ov < s_d[q * 128 + n] ||
                        (ov == s_d[q * 128 + n] && oi < s_i[q * 128 + n])) {
                        s_d[q * 128 + n] = ov; s_i[q * 128 + n] = oi;
                    }
                }
                __syncthreads();
            }
            int idx = s_i[q * 128];
            if (n == 0) g_used[b * 128 + idx] = 1;
            float xv = s_x[q * 128 + n];
            out[((long)b * 128 + idx) * 128 + n] = xv;
            // dec feedback into swizzled Aa[cur] chunks 0-1
            int mtb = b >> 5, rb = b & 31;
            g_Aa[cur][mtb][(n >> 6) * 2048 + swzo(rb, n & 63)] = __float2half_rn(xv);
        }
        group_sync(mt);
    }
}

// ============================================================================
// Launch
// ============================================================================
extern "C" void kernel_launch(void* const* d_in, const int* in_sizes, int n_in,
                              void* d_out, int out_size)
{
    const float* emb  = (const float*)d_in[0];
    const float* node = (const float*)d_in[1];
    const float* W1   = (const float*)d_in[2];
    const float* b1   = (const float*)d_in[3];
    const float* W2   = (const float*)d_in[4];
    const float* b2   = (const float*)d_in[5];
    const float* Wih0 = (const float*)d_in[6];
    const float* Whh0 = (const float*)d_in[7];
    const float* bih0 = (const float*)d_in[8];
    const float* bhh0 = (const float*)d_in[9];
    const float* Wih1 = (const float*)d_in[10];
    const float* Whh1 = (const float*)d_in[11];
    const float* bih1 = (const float*)d_in[12];
    const float* bhh1 = (const float*)d_in[13];
    const float* Wo   = (const float*)d_in[14];
    const float* bo   = (const float*)d_in[15];
    float* out = (float*)d_out;

    cudaFuncSetAttribute(decode_loop, cudaFuncAttributeMaxDynamicSharedMemorySize, GEMM_SMEM);

    float *pW1ft, *pW2ft, *pt, *phx;
    cudaGetSymbolAddress((void**)&pW1ft, g_W1ft);
    cudaGetSymbolAddress((void**)&pW2ft, g_W2ft);
    cudaGetSymbolAddress((void**)&pt,    g_t);
    cudaGetSymbolAddress((void**)&phx,   g_hx);

    prep_weights<<<2048, 256>>>(Wih0, Whh0, bih0, bhh0, Wih1, Whh1, bih1, bhh1, W1, W2);
    sgemm_bias<<<dim3(512 / TBN, BB / TBM), 256>>>(emb, pW1ft, b1, pt, BB, 512, 512, 512, 1);
    sgemm_bias<<<dim3(1024 / TBN, BB / TBM), 256>>>(pt, pW2ft, b2, phx, BB, 1024, 512, 512, 0);
    init_state<<<(BB * HH) / 256, 256>>>();

    decode_loop<<<NCTA, 256, GEMM_SMEM>>>(node, Wo, bo, out);
}